// round 1
// baseline (speedup 1.0000x reference)
#include <cuda_runtime.h>
#include <cuda_bf16.h>
#include <math.h>

// ---------------- static config ----------------
#define B_   8
#define H_   80
#define W_   60
#define C_   512
#define WS_  10
#define SHIFT_ 5
#define NH_  16
#define HD_  32
#define L_   100           // WS*WS
#define NWH_ 8             // H/WS
#define NWW_ 6             // W/WS
#define NW_  48            // NWH*NWW
#define TOK_ (B_*H_*W_)    // 38400
#define FF_  2048          // 4*C

// ---------------- scratch (device globals; no allocations allowed) ----------
__device__ float g_a [(size_t)TOK_*C_];   // LN1-out (windowed) / out-proj out / LN2-out
__device__ float g_q [(size_t)TOK_*C_];
__device__ float g_k [(size_t)TOK_*C_];
__device__ float g_v [(size_t)TOK_*C_];
__device__ float g_c [(size_t)TOK_*C_];   // attention ctx (windowed)
__device__ float g_hs[(size_t)TOK_*C_];   // residual after attention
__device__ float g_f [(size_t)TOK_*FF_];  // FFN hidden

// ---------------- block reduction ----------------
__device__ __forceinline__ float block_sum_128(float v) {
    #pragma unroll
    for (int o = 16; o > 0; o >>= 1) v += __shfl_xor_sync(0xffffffffu, v, o);
    __shared__ float sh[4];
    int lane = threadIdx.x & 31, wid = threadIdx.x >> 5;
    __syncthreads();
    if (lane == 0) sh[wid] = v;
    __syncthreads();
    return sh[0] + sh[1] + sh[2] + sh[3];
}

// ---------------- LN (optionally fused shift + window partition) ------------
// remap=1: output row r is windowed-token r; input row fetched from shifted image.
// remap=0: plain row-wise LN.
__global__ __launch_bounds__(128) void ln_kernel(
    const float* __restrict__ x, const float* __restrict__ g,
    const float* __restrict__ bt, float* __restrict__ out, int remap)
{
    int r = blockIdx.x;
    size_t in_row;
    if (remap) {
        int wg = r / L_, l = r % L_;
        int b = wg / NW_, wi = wg % NW_;
        int wh = wi / NWW_, ww = wi % NWW_;
        int h = (wh * WS_ + l / WS_ + SHIFT_) % H_;
        int w = (ww * WS_ + l % WS_ + SHIFT_) % W_;
        in_row = (size_t)b * (H_ * W_) + h * W_ + w;
    } else {
        in_row = r;
    }
    const float* row = x + in_row * C_;
    float v[4]; float s = 0.f;
    #pragma unroll
    for (int e = 0; e < 4; e++) { v[e] = row[threadIdx.x + e * 128]; s += v[e]; }
    float mean = block_sum_128(s) * (1.f / C_);
    float d2 = 0.f;
    #pragma unroll
    for (int e = 0; e < 4; e++) { float d = v[e] - mean; d2 += d * d; }
    float var = block_sum_128(d2) * (1.f / C_);
    float rstd = rsqrtf(var + 1e-5f);
    float* o = out + (size_t)r * C_;
    #pragma unroll
    for (int e = 0; e < 4; e++) {
        int c = threadIdx.x + e * 128;
        o[c] = (v[e] - mean) * rstd * g[c] + bt[c];
    }
}

// ---------------- tiled fp32 GEMM with fused epilogue -----------------------
// C = A[M,K] @ B[K,N] + bias[N];  epi: 0 none, 1 GELU(exact), 2 +res[M,N]
#define BM 64
#define BN 64
#define BK 16
__global__ __launch_bounds__(256) void gemm_epi_kernel(
    const float* __restrict__ A, const float* __restrict__ Bm,
    const float* __restrict__ bias, const float* __restrict__ res,
    float* __restrict__ C, int M, int N, int K, int epi)
{
    __shared__ float As[BK][BM + 1];
    __shared__ float Bs[BK][BN];
    int bm0 = blockIdx.y * BM, bn0 = blockIdx.x * BN;
    int tid = threadIdx.x;
    int tx = tid & 15, ty = tid >> 4;

    float acc[4][4] = {};
    for (int k0 = 0; k0 < K; k0 += BK) {
        #pragma unroll
        for (int e = 0; e < 4; e++) {
            int idx = tid + e * 256;
            int r = idx >> 4, c = idx & 15;
            As[c][r] = A[(size_t)(bm0 + r) * K + k0 + c];
            int rb = idx >> 6, cb = idx & 63;
            Bs[rb][cb] = Bm[(size_t)(k0 + rb) * N + bn0 + cb];
        }
        __syncthreads();
        #pragma unroll
        for (int kk = 0; kk < BK; kk++) {
            float ra[4], rb[4];
            #pragma unroll
            for (int i = 0; i < 4; i++) ra[i] = As[kk][ty * 4 + i];
            #pragma unroll
            for (int j = 0; j < 4; j++) rb[j] = Bs[kk][tx * 4 + j];
            #pragma unroll
            for (int i = 0; i < 4; i++)
                #pragma unroll
                for (int j = 0; j < 4; j++) acc[i][j] += ra[i] * rb[j];
        }
        __syncthreads();
    }
    #pragma unroll
    for (int i = 0; i < 4; i++) {
        int row = bm0 + ty * 4 + i;
        #pragma unroll
        for (int j = 0; j < 4; j++) {
            int col = bn0 + tx * 4 + j;
            float v = acc[i][j] + bias[col];
            if (epi == 1) {
                v = 0.5f * v * (1.f + erff(v * 0.70710678118654752f));
            } else if (epi == 2) {
                v += res[(size_t)row * N + col];
            }
            C[(size_t)row * N + col] = v;
        }
    }
}

// ---------------- windowed attention ----------------------------------------
// One block per (window, head). q/k/v tiles + scores in dynamic smem.
// Rel-pos bias + shift mask computed in-kernel.
#define QS_STRIDE 33
#define SC_STRIDE 101
__global__ __launch_bounds__(128) void attn_kernel(
    const float* __restrict__ Q, const float* __restrict__ K,
    const float* __restrict__ V, const float* __restrict__ table,
    float* __restrict__ ctx)
{
    int w = blockIdx.x;          // global window 0..383
    int head = blockIdx.y;       // 0..15
    int wi = w % NW_;
    int wh = wi / NWW_, ww = wi % NWW_;

    extern __shared__ float sm[];
    float* qs = sm;                         // L_ * QS_STRIDE
    float* ks = qs + L_ * QS_STRIDE;        // L_ * HD_
    float* vs = ks + L_ * HD_;              // L_ * HD_
    float* sc = vs + L_ * HD_;              // L_ * SC_STRIDE

    __shared__ int   lab[L_];
    __shared__ float stable[(2 * WS_ - 1) * (2 * WS_ - 1)];  // 361

    int tid = threadIdx.x;
    for (int idx = tid; idx < L_ * HD_; idx += 128) {
        int l = idx >> 5, d = idx & 31;
        size_t gi = ((size_t)(w * L_ + l)) * C_ + head * HD_ + d;
        qs[l * QS_STRIDE + d] = Q[gi];
        ks[idx] = K[gi];
        vs[idx] = V[gi];
    }
    for (int idx = tid; idx < 361; idx += 128) stable[idx] = table[idx * NH_ + head];
    if (tid < L_) {
        int i = tid / WS_, j = tid % WS_;
        int h = wh * WS_ + i, x = ww * WS_ + j;
        int rh = (h < H_ - WS_) ? 0 : ((h < H_ - SHIFT_) ? 1 : 2);
        int rw = (x < W_ - WS_) ? 0 : ((x < W_ - SHIFT_) ? 1 : 2);
        lab[tid] = rh * 3 + rw;
    }
    __syncthreads();

    if (tid < L_) {
        const float scale = 0.17677669529663687f;  // 1/sqrt(32)
        int i1 = tid / WS_, j1 = tid % WS_;
        int lq = lab[tid];
        float* my = &sc[tid * SC_STRIDE];
        for (int kj = 0; kj < L_; kj++) {
            float acc = 0.f;
            #pragma unroll
            for (int d = 0; d < HD_; d++)
                acc += qs[tid * QS_STRIDE + d] * ks[kj * HD_ + d];
            int i2 = kj / WS_, j2 = kj % WS_;
            int ridx = (i1 - i2 + WS_ - 1) * (2 * WS_ - 1) + (j1 - j2 + WS_ - 1);
            float m = (lab[kj] != lq) ? -100.f : 0.f;
            my[kj] = acc * scale + stable[ridx] + m;
        }
        // softmax
        float mx = -1e30f;
        for (int kj = 0; kj < L_; kj++) mx = fmaxf(mx, my[kj]);
        float sum = 0.f;
        for (int kj = 0; kj < L_; kj++) { float e = expf(my[kj] - mx); my[kj] = e; sum += e; }
        float inv = 1.f / sum;
        // ctx = attn @ V
        float acc[HD_];
        #pragma unroll
        for (int d = 0; d < HD_; d++) acc[d] = 0.f;
        for (int kj = 0; kj < L_; kj++) {
            float p = my[kj] * inv;
            #pragma unroll
            for (int d = 0; d < HD_; d++) acc[d] += p * vs[kj * HD_ + d];
        }
        size_t go = ((size_t)(w * L_ + tid)) * C_ + head * HD_;
        #pragma unroll
        for (int d = 0; d < HD_; d++) ctx[go + d] = acc[d];
    }
}

// ---------------- window reverse + un-shift + residual ----------------------
__global__ __launch_bounds__(256) void reverse_residual_kernel(
    const float* __restrict__ hidden, const float* __restrict__ att,
    float* __restrict__ hs)
{
    size_t idx = (size_t)blockIdx.x * 256 + threadIdx.x;  // over TOK_*C_
    int t = (int)(idx >> 9);       // token
    int c = (int)(idx & 511);
    int b = t / (H_ * W_), p = t % (H_ * W_);
    int h = p / W_, w = p % W_;
    int hp = (h + H_ - SHIFT_) % H_;
    int wp = (w + W_ - SHIFT_) % W_;
    int wh = hp / WS_, i = hp % WS_, ww = wp / WS_, j = wp % WS_;
    int src = (b * NW_ + wh * NWW_ + ww) * L_ + i * WS_ + j;
    hs[idx] = hidden[idx] + att[(size_t)src * C_ + c];
}

// ---------------- driver ----------------------------------------------------
extern "C" void kernel_launch(void* const* d_in, const int* in_sizes, int n_in,
                              void* d_out, int out_size)
{
    const float* hidden = (const float*)d_in[0];
    const float* ln1_g  = (const float*)d_in[1];
    const float* ln1_b  = (const float*)d_in[2];
    const float* wq = (const float*)d_in[3];
    const float* bq = (const float*)d_in[4];
    const float* wk = (const float*)d_in[5];
    const float* bk = (const float*)d_in[6];
    const float* wv = (const float*)d_in[7];
    const float* bv = (const float*)d_in[8];
    const float* wo = (const float*)d_in[9];
    const float* bo = (const float*)d_in[10];
    const float* table = (const float*)d_in[11];
    const float* ln2_g = (const float*)d_in[12];
    const float* ln2_b = (const float*)d_in[13];
    const float* w1 = (const float*)d_in[14];
    const float* b1 = (const float*)d_in[15];
    const float* w2 = (const float*)d_in[16];
    const float* b2 = (const float*)d_in[17];
    float* out = (float*)d_out;

    float *pa, *pq, *pk, *pv, *pc, *phs, *pf;
    cudaGetSymbolAddress((void**)&pa,  g_a);
    cudaGetSymbolAddress((void**)&pq,  g_q);
    cudaGetSymbolAddress((void**)&pk,  g_k);
    cudaGetSymbolAddress((void**)&pv,  g_v);
    cudaGetSymbolAddress((void**)&pc,  g_c);
    cudaGetSymbolAddress((void**)&phs, g_hs);
    cudaGetSymbolAddress((void**)&pf,  g_f);

    // 1) LN1 + shift + window partition  -> g_a (windowed layout, 38400 x 512)
    ln_kernel<<<TOK_, 128>>>(hidden, ln1_g, ln1_b, pa, 1);

    // 2) QKV projections
    dim3 g512(C_ / BN, TOK_ / BM);
    gemm_epi_kernel<<<g512, 256>>>(pa, wq, bq, nullptr, pq, TOK_, C_, C_, 0);
    gemm_epi_kernel<<<g512, 256>>>(pa, wk, bk, nullptr, pk, TOK_, C_, C_, 0);
    gemm_epi_kernel<<<g512, 256>>>(pa, wv, bv, nullptr, pv, TOK_, C_, C_, 0);

    // 3) windowed attention -> g_c
    size_t smem = (size_t)(L_ * QS_STRIDE + 2 * L_ * HD_ + L_ * SC_STRIDE) * sizeof(float);
    cudaFuncSetAttribute(attn_kernel, cudaFuncAttributeMaxDynamicSharedMemorySize, (int)smem);
    attn_kernel<<<dim3(B_ * NW_, NH_), 128, smem>>>(pq, pk, pv, table, pc);

    // 4) output projection -> g_a
    gemm_epi_kernel<<<g512, 256>>>(pc, wo, bo, nullptr, pa, TOK_, C_, C_, 0);

    // 5) window reverse + un-shift + residual -> g_hs
    reverse_residual_kernel<<<(TOK_ * C_) / 256, 256>>>(hidden, pa, phs);

    // 6) LN2 -> g_a
    ln_kernel<<<TOK_, 128>>>(phs, ln2_g, ln2_b, pa, 0);

    // 7) FFN1 with fused exact GELU -> g_f
    gemm_epi_kernel<<<dim3(FF_ / BN, TOK_ / BM), 256>>>(pa, w1, b1, nullptr, pf,
                                                        TOK_, FF_, C_, 1);

    // 8) FFN2 + residual -> out
    gemm_epi_kernel<<<g512, 256>>>(pf, w2, b2, phs, out, TOK_, C_, FF_, 2);
}

// round 3
// speedup vs baseline: 2.8244x; 2.8244x over previous
#include <cuda_runtime.h>
#include <cuda_bf16.h>
#include <math.h>
#include <stdint.h>

// ---------------- static config ----------------
#define B_   8
#define H_   80
#define W_   60
#define C_   512
#define WS_  10
#define SHIFT_ 5
#define NH_  16
#define HD_  32
#define L_   100
#define NWH_ 8
#define NWW_ 6
#define NW_  48
#define TOK_ (B_*H_*W_)    // 38400
#define FF_  2048

// ---------------- scratch ----------------
__device__ float g_a [(size_t)TOK_*C_];
__device__ float g_q [(size_t)TOK_*C_];
__device__ float g_k [(size_t)TOK_*C_];
__device__ float g_v [(size_t)TOK_*C_];
__device__ float g_c [(size_t)TOK_*C_];
__device__ float g_hs[(size_t)TOK_*C_];
__device__ float g_f [(size_t)TOK_*FF_];

// ---------------- helpers ----------------
__device__ __forceinline__ uint32_t smem_u32(const void* p) {
    uint32_t a;
    asm("{ .reg .u64 t; cvta.to.shared.u64 t, %1; cvt.u32.u64 %0, t; }" : "=r"(a) : "l"(p));
    return a;
}
__device__ __forceinline__ void cp16(uint32_t s, const void* g) {
    asm volatile("cp.async.cg.shared.global [%0], [%1], 16;" :: "r"(s), "l"(g) : "memory");
}
__device__ __forceinline__ float to_tf32(float x) {
    uint32_t o; asm("cvt.rna.tf32.f32 %0, %1;" : "=r"(o) : "f"(x));
    return __uint_as_float(o);
}
__device__ __forceinline__ void mma_tf32(float* d, const float* a, const float* b) {
    const uint32_t* A = reinterpret_cast<const uint32_t*>(a);
    const uint32_t* B = reinterpret_cast<const uint32_t*>(b);
    asm volatile(
        "mma.sync.aligned.m16n8k8.row.col.f32.tf32.tf32.f32 "
        "{%0,%1,%2,%3}, {%4,%5,%6,%7}, {%8,%9}, {%0,%1,%2,%3};"
        : "+f"(d[0]), "+f"(d[1]), "+f"(d[2]), "+f"(d[3])
        : "r"(A[0]), "r"(A[1]), "r"(A[2]), "r"(A[3]), "r"(B[0]), "r"(B[1]));
}

// ---------------- block reduction for LN ----------------
__device__ __forceinline__ float block_sum_128(float v) {
    #pragma unroll
    for (int o = 16; o > 0; o >>= 1) v += __shfl_xor_sync(0xffffffffu, v, o);
    __shared__ float sh[4];
    int lane = threadIdx.x & 31, wid = threadIdx.x >> 5;
    __syncthreads();
    if (lane == 0) sh[wid] = v;
    __syncthreads();
    return sh[0] + sh[1] + sh[2] + sh[3];
}

// ---------------- LN (optionally fused shift + window partition) ------------
__global__ __launch_bounds__(128) void ln_kernel(
    const float* __restrict__ x, const float* __restrict__ g,
    const float* __restrict__ bt, float* __restrict__ out, int remap)
{
    int r = blockIdx.x;
    size_t in_row;
    if (remap) {
        int wg = r / L_, l = r % L_;
        int b = wg / NW_, wi = wg % NW_;
        int wh = wi / NWW_, ww = wi % NWW_;
        int h = (wh * WS_ + l / WS_ + SHIFT_) % H_;
        int w = (ww * WS_ + l % WS_ + SHIFT_) % W_;
        in_row = (size_t)b * (H_ * W_) + h * W_ + w;
    } else in_row = r;
    const float* row = x + in_row * C_;
    float v[4]; float s = 0.f;
    #pragma unroll
    for (int e = 0; e < 4; e++) { v[e] = row[threadIdx.x + e * 128]; s += v[e]; }
    float mean = block_sum_128(s) * (1.f / C_);
    float d2 = 0.f;
    #pragma unroll
    for (int e = 0; e < 4; e++) { float d = v[e] - mean; d2 += d * d; }
    float var = block_sum_128(d2) * (1.f / C_);
    float rstd = rsqrtf(var + 1e-5f);
    float* o = out + (size_t)r * C_;
    #pragma unroll
    for (int e = 0; e < 4; e++) {
        int c = threadIdx.x + e * 128;
        o[c] = (v[e] - mean) * rstd * g[c] + bt[c];
    }
}

// ---------------- tf32 mma.sync GEMM ----------------------------------------
// out[tok, n] = sum_k Act[tok, k] * W[k, n] + bias[n] (+GELU | +res)
// CTA tile 128x128x32, 8 warps of 64x32. Double-buffered cp.async.
#define BM 128
#define BN 128
#define BK 32
#define AST 36     // A smem row stride (floats): banks 4r+c, conflict-free
#define BST 136    // B smem row stride (floats): banks 8c+n, conflict-free

__global__ __launch_bounds__(256) void gemm_mma(
    const float* __restrict__ Act, const float* __restrict__ Wt,
    const float* __restrict__ bias, const float* __restrict__ res,
    float* __restrict__ out, int Nout, int K, int epi)
{
    extern __shared__ float sm[];
    float* Abuf[2] = { sm, sm + BM * AST };
    float* Bbuf[2] = { sm + 2 * BM * AST, sm + 2 * BM * AST + BK * BST };

    int tid = threadIdx.x, lane = tid & 31, wid = tid >> 5;
    int tok0 = blockIdx.x * BM, n0 = blockIdx.y * BN;
    int wm0 = (wid & 1) * 64, wn0 = (wid >> 1) * 32;

    float acc[4][4][4];
    #pragma unroll
    for (int mt = 0; mt < 4; mt++)
        #pragma unroll
        for (int nt = 0; nt < 4; nt++)
            #pragma unroll
            for (int e = 0; e < 4; e++) acc[mt][nt][e] = 0.f;

    const int nch = K / BK;

    // prologue: chunk 0
    {
        int buf = 0, k0 = 0;
        #pragma unroll
        for (int i = 0; i < 4; i++) {
            int idx = tid + i * 256;
            int row = idx >> 3, seg = idx & 7;
            cp16(smem_u32(Abuf[buf] + row * AST + seg * 4),
                 Act + (size_t)(tok0 + row) * K + k0 + seg * 4);
        }
        #pragma unroll
        for (int i = 0; i < 4; i++) {
            int idx = tid + i * 256;
            int row = idx >> 5, seg = idx & 31;
            cp16(smem_u32(Bbuf[buf] + row * BST + seg * 4),
                 Wt + (size_t)(k0 + row) * Nout + n0 + seg * 4);
        }
        asm volatile("cp.async.commit_group;" ::: "memory");
    }

    for (int c = 0; c < nch; c++) {
        if (c + 1 < nch) {
            int buf = (c + 1) & 1, k0 = (c + 1) * BK;
            #pragma unroll
            for (int i = 0; i < 4; i++) {
                int idx = tid + i * 256;
                int row = idx >> 3, seg = idx & 7;
                cp16(smem_u32(Abuf[buf] + row * AST + seg * 4),
                     Act + (size_t)(tok0 + row) * K + k0 + seg * 4);
            }
            #pragma unroll
            for (int i = 0; i < 4; i++) {
                int idx = tid + i * 256;
                int row = idx >> 5, seg = idx & 31;
                cp16(smem_u32(Bbuf[buf] + row * BST + seg * 4),
                     Wt + (size_t)(k0 + row) * Nout + n0 + seg * 4);
            }
            asm volatile("cp.async.commit_group;" ::: "memory");
            asm volatile("cp.async.wait_group 1;" ::: "memory");
        } else {
            asm volatile("cp.async.wait_group 0;" ::: "memory");
        }
        __syncthreads();

        const float* A = Abuf[c & 1];
        const float* Bm = Bbuf[c & 1];
        #pragma unroll
        for (int ks = 0; ks < 4; ks++) {
            float a[4][4], b[4][2];
            int arow = lane >> 2, acol = ks * 8 + (lane & 3);
            #pragma unroll
            for (int mt = 0; mt < 4; mt++) {
                int r = wm0 + mt * 16 + arow;
                a[mt][0] = to_tf32(A[r * AST + acol]);
                a[mt][1] = to_tf32(A[(r + 8) * AST + acol]);
                a[mt][2] = to_tf32(A[r * AST + acol + 4]);
                a[mt][3] = to_tf32(A[(r + 8) * AST + acol + 4]);
            }
            int brow0 = (ks * 8 + (lane & 3)) * BST;
            int brow1 = (ks * 8 + 4 + (lane & 3)) * BST;
            #pragma unroll
            for (int nt = 0; nt < 4; nt++) {
                int cn = wn0 + nt * 8 + (lane >> 2);
                b[nt][0] = to_tf32(Bm[brow0 + cn]);
                b[nt][1] = to_tf32(Bm[brow1 + cn]);
            }
            #pragma unroll
            for (int mt = 0; mt < 4; mt++)
                #pragma unroll
                for (int nt = 0; nt < 4; nt++)
                    mma_tf32(acc[mt][nt], a[mt], b[nt]);
        }
        __syncthreads();
    }

    // ---- epilogue ----
    #pragma unroll
    for (int mt = 0; mt < 4; mt++) {
        #pragma unroll
        for (int nt = 0; nt < 4; nt++) {
            int r0 = tok0 + wm0 + mt * 16 + (lane >> 2);
            int c0 = n0 + wn0 + nt * 8 + 2 * (lane & 3);
            float2 bv = *(const float2*)(bias + c0);
            #pragma unroll
            for (int h = 0; h < 2; h++) {
                int row = r0 + h * 8;
                float v0 = acc[mt][nt][2 * h + 0] + bv.x;
                float v1 = acc[mt][nt][2 * h + 1] + bv.y;
                if (epi == 1) {
                    v0 = 0.5f * v0 * (1.f + erff(v0 * 0.70710678118654752f));
                    v1 = 0.5f * v1 * (1.f + erff(v1 * 0.70710678118654752f));
                } else if (epi == 2) {
                    float2 rr = *(const float2*)(res + (size_t)row * Nout + c0);
                    v0 += rr.x; v1 += rr.y;
                }
                float2 o; o.x = v0; o.y = v1;
                *(float2*)(out + (size_t)row * Nout + c0) = o;
            }
        }
    }
}

// ---------------- windowed attention (online softmax, q in regs) ------------
__global__ __launch_bounds__(128) void attn_kernel(
    const float* __restrict__ Q, const float* __restrict__ K,
    const float* __restrict__ V, const float* __restrict__ table,
    float* __restrict__ ctx)
{
    int w = blockIdx.x;
    int head = blockIdx.y;
    int wi = w % NW_;
    int wh = wi / NWW_, ww = wi % NWW_;

    __shared__ float ks[L_ * HD_];
    __shared__ float vs[L_ * HD_];
    __shared__ float stable[(2 * WS_ - 1) * (2 * WS_ - 1)];
    __shared__ int   lab[L_];

    int tid = threadIdx.x;
    for (int idx = tid; idx < L_ * HD_; idx += 128) {
        int l = idx >> 5, d = idx & 31;
        size_t gi = ((size_t)(w * L_ + l)) * C_ + head * HD_ + d;
        ks[idx] = K[gi];
        vs[idx] = V[gi];
    }
    for (int idx = tid; idx < 361; idx += 128) stable[idx] = table[idx * NH_ + head];
    if (tid < L_) {
        int i = tid / WS_, j = tid % WS_;
        int h = wh * WS_ + i, x = ww * WS_ + j;
        int rh = (h < H_ - WS_) ? 0 : ((h < H_ - SHIFT_) ? 1 : 2);
        int rw = (x < W_ - WS_) ? 0 : ((x < W_ - SHIFT_) ? 1 : 2);
        lab[tid] = rh * 3 + rw;
    }
    __syncthreads();

    if (tid < L_) {
        const float scale = 0.17677669529663687f;
        int i1 = tid / WS_, j1 = tid % WS_;
        int lq = lab[tid];
        float4 q[8];
        const float4* qg = (const float4*)(Q + ((size_t)(w * L_ + tid)) * C_ + head * HD_);
        #pragma unroll
        for (int t = 0; t < 8; t++) q[t] = qg[t];

        float m = -1e30f, ssum = 0.f;
        float4 acc[8];
        #pragma unroll
        for (int t = 0; t < 8; t++) acc[t] = make_float4(0.f, 0.f, 0.f, 0.f);

        for (int ch = 0; ch < WS_; ch++) {
            float sc[WS_];
            float cmax = -1e30f;
            int rowoff = (i1 - ch + WS_ - 1) * (2 * WS_ - 1);
            #pragma unroll
            for (int u = 0; u < WS_; u++) {
                int kj = ch * WS_ + u;
                const float4* kk = (const float4*)&ks[kj * HD_];
                float dsum = 0.f;
                #pragma unroll
                for (int t = 0; t < 8; t++) {
                    float4 kv = kk[t];
                    dsum += q[t].x * kv.x + q[t].y * kv.y + q[t].z * kv.z + q[t].w * kv.w;
                }
                float msk = (lab[kj] != lq) ? -100.f : 0.f;
                sc[u] = dsum * scale + stable[rowoff + (j1 - u + WS_ - 1)] + msk;
                cmax = fmaxf(cmax, sc[u]);
            }
            float nm = fmaxf(m, cmax);
            float corr = __expf(m - nm);
            ssum *= corr;
            #pragma unroll
            for (int t = 0; t < 8; t++) {
                acc[t].x *= corr; acc[t].y *= corr; acc[t].z *= corr; acc[t].w *= corr;
            }
            #pragma unroll
            for (int u = 0; u < WS_; u++) {
                float p = __expf(sc[u] - nm);
                ssum += p;
                const float4* vv = (const float4*)&vs[(ch * WS_ + u) * HD_];
                #pragma unroll
                for (int t = 0; t < 8; t++) {
                    float4 vb = vv[t];
                    acc[t].x += p * vb.x; acc[t].y += p * vb.y;
                    acc[t].z += p * vb.z; acc[t].w += p * vb.w;
                }
            }
            m = nm;
        }
        float inv = 1.f / ssum;
        float4* og = (float4*)(ctx + ((size_t)(w * L_ + tid)) * C_ + head * HD_);
        #pragma unroll
        for (int t = 0; t < 8; t++) {
            float4 o;
            o.x = acc[t].x * inv; o.y = acc[t].y * inv;
            o.z = acc[t].z * inv; o.w = acc[t].w * inv;
            og[t] = o;
        }
    }
}

// ---------------- window reverse + un-shift + residual ----------------------
__global__ __launch_bounds__(256) void reverse_residual_kernel(
    const float* __restrict__ hidden, const float* __restrict__ att,
    float* __restrict__ hs)
{
    size_t idx = (size_t)blockIdx.x * 256 + threadIdx.x;
    int t = (int)(idx >> 9);
    int c = (int)(idx & 511);
    int b = t / (H_ * W_), p = t % (H_ * W_);
    int h = p / W_, w = p % W_;
    int hp = (h + H_ - SHIFT_) % H_;
    int wp = (w + W_ - SHIFT_) % W_;
    int wh = hp / WS_, i = hp % WS_, ww = wp / WS_, j = wp % WS_;
    int src = (b * NW_ + wh * NWW_ + ww) * L_ + i * WS_ + j;
    hs[idx] = hidden[idx] + att[(size_t)src * C_ + c];
}

// ---------------- driver ----------------------------------------------------
extern "C" void kernel_launch(void* const* d_in, const int* in_sizes, int n_in,
                              void* d_out, int out_size)
{
    const float* hidden = (const float*)d_in[0];
    const float* ln1_g  = (const float*)d_in[1];
    const float* ln1_b  = (const float*)d_in[2];
    const float* wq = (const float*)d_in[3];
    const float* bq = (const float*)d_in[4];
    const float* wk = (const float*)d_in[5];
    const float* bk = (const float*)d_in[6];
    const float* wv = (const float*)d_in[7];
    const float* bv = (const float*)d_in[8];
    const float* wo = (const float*)d_in[9];
    const float* bo = (const float*)d_in[10];
    const float* table = (const float*)d_in[11];
    const float* ln2_g = (const float*)d_in[12];
    const float* ln2_b = (const float*)d_in[13];
    const float* w1 = (const float*)d_in[14];
    const float* b1 = (const float*)d_in[15];
    const float* w2 = (const float*)d_in[16];
    const float* b2 = (const float*)d_in[17];
    float* out = (float*)d_out;

    float *pa, *pq, *pk, *pv, *pc, *phs, *pf;
    cudaGetSymbolAddress((void**)&pa,  g_a);
    cudaGetSymbolAddress((void**)&pq,  g_q);
    cudaGetSymbolAddress((void**)&pk,  g_k);
    cudaGetSymbolAddress((void**)&pv,  g_v);
    cudaGetSymbolAddress((void**)&pc,  g_c);
    cudaGetSymbolAddress((void**)&phs, g_hs);
    cudaGetSymbolAddress((void**)&pf,  g_f);

    const int GSMEM = (2 * BM * AST + 2 * BK * BST) * 4;  // 71680 bytes
    cudaFuncSetAttribute(gemm_mma, cudaFuncAttributeMaxDynamicSharedMemorySize, GSMEM);

    // 1) LN1 + shift + window partition -> g_a
    ln_kernel<<<TOK_, 128>>>(hidden, ln1_g, ln1_b, pa, 1);

    // 2) QKV projections
    dim3 gp(TOK_ / BM, C_ / BN);
    gemm_mma<<<gp, 256, GSMEM>>>(pa, wq, bq, nullptr, pq, C_, C_, 0);
    gemm_mma<<<gp, 256, GSMEM>>>(pa, wk, bk, nullptr, pk, C_, C_, 0);
    gemm_mma<<<gp, 256, GSMEM>>>(pa, wv, bv, nullptr, pv, C_, C_, 0);

    // 3) windowed attention -> g_c
    attn_kernel<<<dim3(B_ * NW_, NH_), 128>>>(pq, pk, pv, table, pc);

    // 4) output projection -> g_a
    gemm_mma<<<gp, 256, GSMEM>>>(pc, wo, bo, nullptr, pa, C_, C_, 0);

    // 5) window reverse + un-shift + residual -> g_hs
    reverse_residual_kernel<<<(TOK_ * C_) / 256, 256>>>(hidden, pa, phs);

    // 6) LN2 -> g_a
    ln_kernel<<<TOK_, 128>>>(phs, ln2_g, ln2_b, pa, 0);

    // 7) FFN1 + GELU -> g_f
    gemm_mma<<<dim3(TOK_ / BM, FF_ / BN), 256, GSMEM>>>(pa, w1, b1, nullptr, pf, FF_, C_, 1);

    // 8) FFN2 + residual -> out
    gemm_mma<<<gp, 256, GSMEM>>>(pf, w2, b2, phs, out, C_, FF_, 2);
}

// round 4
// speedup vs baseline: 3.6340x; 1.2866x over previous
#include <cuda_runtime.h>
#include <cuda_bf16.h>
#include <math.h>
#include <stdint.h>

// ---------------- static config ----------------
#define B_   8
#define H_   80
#define W_   60
#define C_   512
#define WS_  10
#define SHIFT_ 5
#define NH_  16
#define HD_  32
#define L_   100
#define NWH_ 8
#define NWW_ 6
#define NW_  48
#define TOK_ (B_*H_*W_)    // 38400
#define FF_  2048

// ---------------- scratch ----------------
__device__ float g_a [(size_t)TOK_*C_];
__device__ float g_q [(size_t)TOK_*C_];
__device__ float g_k [(size_t)TOK_*C_];
__device__ float g_v [(size_t)TOK_*C_];
__device__ float g_c [(size_t)TOK_*C_];
__device__ float g_hs[(size_t)TOK_*C_];
__device__ float g_f [(size_t)TOK_*FF_];

// ---------------- helpers ----------------
__device__ __forceinline__ uint32_t smem_u32(const void* p) {
    uint32_t a;
    asm("{ .reg .u64 t; cvta.to.shared.u64 t, %1; cvt.u32.u64 %0, t; }" : "=r"(a) : "l"(p));
    return a;
}
__device__ __forceinline__ void cp16(uint32_t s, const void* g) {
    asm volatile("cp.async.cg.shared.global [%0], [%1], 16;" :: "r"(s), "l"(g) : "memory");
}
__device__ __forceinline__ void mma_tf32(float* d, const float* a, const float* b) {
    const uint32_t* A = reinterpret_cast<const uint32_t*>(a);
    const uint32_t* B = reinterpret_cast<const uint32_t*>(b);
    asm volatile(
        "mma.sync.aligned.m16n8k8.row.col.f32.tf32.tf32.f32 "
        "{%0,%1,%2,%3}, {%4,%5,%6,%7}, {%8,%9}, {%0,%1,%2,%3};"
        : "+f"(d[0]), "+f"(d[1]), "+f"(d[2]), "+f"(d[3])
        : "r"(A[0]), "r"(A[1]), "r"(A[2]), "r"(A[3]), "r"(B[0]), "r"(B[1]));
}

// ---------------- block reduction for LN ----------------
__device__ __forceinline__ float block_sum_128(float v) {
    #pragma unroll
    for (int o = 16; o > 0; o >>= 1) v += __shfl_xor_sync(0xffffffffu, v, o);
    __shared__ float sh[4];
    int lane = threadIdx.x & 31, wid = threadIdx.x >> 5;
    __syncthreads();
    if (lane == 0) sh[wid] = v;
    __syncthreads();
    return sh[0] + sh[1] + sh[2] + sh[3];
}

// ---------------- LN (optionally fused shift + window partition) ------------
__global__ __launch_bounds__(128) void ln_kernel(
    const float* __restrict__ x, const float* __restrict__ g,
    const float* __restrict__ bt, float* __restrict__ out, int remap)
{
    int r = blockIdx.x;
    size_t in_row;
    if (remap) {
        int wg = r / L_, l = r % L_;
        int b = wg / NW_, wi = wg % NW_;
        int wh = wi / NWW_, ww = wi % NWW_;
        int h = (wh * WS_ + l / WS_ + SHIFT_) % H_;
        int w = (ww * WS_ + l % WS_ + SHIFT_) % W_;
        in_row = (size_t)b * (H_ * W_) + h * W_ + w;
    } else in_row = r;
    const float* row = x + in_row * C_;
    float v[4]; float s = 0.f;
    #pragma unroll
    for (int e = 0; e < 4; e++) { v[e] = row[threadIdx.x + e * 128]; s += v[e]; }
    float mean = block_sum_128(s) * (1.f / C_);
    float d2 = 0.f;
    #pragma unroll
    for (int e = 0; e < 4; e++) { float d = v[e] - mean; d2 += d * d; }
    float var = block_sum_128(d2) * (1.f / C_);
    float rstd = rsqrtf(var + 1e-5f);
    float* o = out + (size_t)r * C_;
    #pragma unroll
    for (int e = 0; e < 4; e++) {
        int c = threadIdx.x + e * 128;
        o[c] = (v[e] - mean) * rstd * g[c] + bt[c];
    }
}

// ---------------- tf32 mma.sync GEMM (3-stage, no in-loop cvt) --------------
#define BM 128
#define BN 128
#define BK 32
#define AST 36
#define BST 136
#define STG_F (BM * AST + BK * BST)   // floats per stage: 8960

__global__ __launch_bounds__(256) void gemm_mma(
    const float* __restrict__ Act, const float* __restrict__ Wt,
    const float* __restrict__ bias, const float* __restrict__ res,
    float* __restrict__ out, int Nout, int K, int epi)
{
    extern __shared__ float sm[];

    int tid = threadIdx.x, lane = tid & 31, wid = tid >> 5;
    int tok0 = blockIdx.x * BM, n0 = blockIdx.y * BN;
    int wm0 = (wid & 1) * 64, wn0 = (wid >> 1) * 32;

    // precomputed load indices
    int a_row = tid >> 3, a_seg = tid & 7;          // + i*32 rows
    int b_row = tid >> 5, b_seg = tid & 31;         // + i*8 rows
    const float* a_gp = Act + (size_t)(tok0 + a_row) * K + a_seg * 4;
    const float* b_gp = Wt + (size_t)b_row * Nout + n0 + b_seg * 4;

    float acc[4][4][4];
    #pragma unroll
    for (int mt = 0; mt < 4; mt++)
        #pragma unroll
        for (int nt = 0; nt < 4; nt++)
            #pragma unroll
            for (int e = 0; e < 4; e++) acc[mt][nt][e] = 0.f;

    const int nch = K / BK;

    auto issue = [&](int c) {
        int s = c % 3;
        float* Ab = sm + s * STG_F;
        float* Bb = Ab + BM * AST;
        int k0 = c * BK;
        #pragma unroll
        for (int i = 0; i < 4; i++)
            cp16(smem_u32(Ab + (a_row + i * 32) * AST + a_seg * 4),
                 a_gp + (size_t)(i * 32) * K + k0);
        #pragma unroll
        for (int i = 0; i < 4; i++)
            cp16(smem_u32(Bb + (b_row + i * 8) * BST + b_seg * 4),
                 b_gp + (size_t)(k0 + i * 8) * Nout);
        asm volatile("cp.async.commit_group;" ::: "memory");
    };

    issue(0);
    if (nch > 1) issue(1);

    for (int c = 0; c < nch; c++) {
        if (c + 2 < nch) {
            issue(c + 2);
            asm volatile("cp.async.wait_group 2;" ::: "memory");
        } else if (c + 1 < nch) {
            asm volatile("cp.async.wait_group 1;" ::: "memory");
        } else {
            asm volatile("cp.async.wait_group 0;" ::: "memory");
        }
        __syncthreads();

        int s = c % 3;
        const float* A = sm + s * STG_F;
        const float* Bm = A + BM * AST;
        #pragma unroll
        for (int ks = 0; ks < 4; ks++) {
            float a[4][4], b[4][2];
            int arow = lane >> 2, acol = ks * 8 + (lane & 3);
            #pragma unroll
            for (int mt = 0; mt < 4; mt++) {
                int r = wm0 + mt * 16 + arow;
                a[mt][0] = A[r * AST + acol];
                a[mt][1] = A[(r + 8) * AST + acol];
                a[mt][2] = A[r * AST + acol + 4];
                a[mt][3] = A[(r + 8) * AST + acol + 4];
            }
            int brow0 = (ks * 8 + (lane & 3)) * BST;
            int brow1 = (ks * 8 + 4 + (lane & 3)) * BST;
            #pragma unroll
            for (int nt = 0; nt < 4; nt++) {
                int cn = wn0 + nt * 8 + (lane >> 2);
                b[nt][0] = Bm[brow0 + cn];
                b[nt][1] = Bm[brow1 + cn];
            }
            #pragma unroll
            for (int mt = 0; mt < 4; mt++)
                #pragma unroll
                for (int nt = 0; nt < 4; nt++)
                    mma_tf32(acc[mt][nt], a[mt], b[nt]);
        }
        __syncthreads();
    }

    // ---- epilogue ----
    #pragma unroll
    for (int mt = 0; mt < 4; mt++) {
        #pragma unroll
        for (int nt = 0; nt < 4; nt++) {
            int r0 = tok0 + wm0 + mt * 16 + (lane >> 2);
            int c0 = n0 + wn0 + nt * 8 + 2 * (lane & 3);
            float2 bv = *(const float2*)(bias + c0);
            #pragma unroll
            for (int h = 0; h < 2; h++) {
                int row = r0 + h * 8;
                float v0 = acc[mt][nt][2 * h + 0] + bv.x;
                float v1 = acc[mt][nt][2 * h + 1] + bv.y;
                if (epi == 1) {
                    v0 = 0.5f * v0 * (1.f + erff(v0 * 0.70710678118654752f));
                    v1 = 0.5f * v1 * (1.f + erff(v1 * 0.70710678118654752f));
                } else if (epi == 2) {
                    float2 rr = *(const float2*)(res + (size_t)row * Nout + c0);
                    v0 += rr.x; v1 += rr.y;
                }
                float2 o; o.x = v0; o.y = v1;
                *(float2*)(out + (size_t)row * Nout + c0) = o;
            }
        }
    }
}

// ---------------- windowed attention (online softmax, q in regs) ------------
__global__ __launch_bounds__(128) void attn_kernel(
    const float* __restrict__ Q, const float* __restrict__ K,
    const float* __restrict__ V, const float* __restrict__ table,
    float* __restrict__ ctx)
{
    int w = blockIdx.x;
    int head = blockIdx.y;
    int wi = w % NW_;
    int wh = wi / NWW_, ww = wi % NWW_;

    __shared__ float ks[L_ * HD_];
    __shared__ float vs[L_ * HD_];
    __shared__ float stable[(2 * WS_ - 1) * (2 * WS_ - 1)];
    __shared__ int   lab[L_];

    int tid = threadIdx.x;
    for (int idx = tid; idx < L_ * HD_; idx += 128) {
        int l = idx >> 5, d = idx & 31;
        size_t gi = ((size_t)(w * L_ + l)) * C_ + head * HD_ + d;
        ks[idx] = K[gi];
        vs[idx] = V[gi];
    }
    for (int idx = tid; idx < 361; idx += 128) stable[idx] = table[idx * NH_ + head];
    if (tid < L_) {
        int i = tid / WS_, j = tid % WS_;
        int h = wh * WS_ + i, x = ww * WS_ + j;
        int rh = (h < H_ - WS_) ? 0 : ((h < H_ - SHIFT_) ? 1 : 2);
        int rw = (x < W_ - WS_) ? 0 : ((x < W_ - SHIFT_) ? 1 : 2);
        lab[tid] = rh * 3 + rw;
    }
    __syncthreads();

    if (tid < L_) {
        const float scale = 0.17677669529663687f;
        int i1 = tid / WS_, j1 = tid % WS_;
        int lq = lab[tid];
        float4 q[8];
        const float4* qg = (const float4*)(Q + ((size_t)(w * L_ + tid)) * C_ + head * HD_);
        #pragma unroll
        for (int t = 0; t < 8; t++) q[t] = qg[t];

        float m = -1e30f, ssum = 0.f;
        float4 acc[8];
        #pragma unroll
        for (int t = 0; t < 8; t++) acc[t] = make_float4(0.f, 0.f, 0.f, 0.f);

        for (int ch = 0; ch < WS_; ch++) {
            float sc[WS_];
            float cmax = -1e30f;
            int rowoff = (i1 - ch + WS_ - 1) * (2 * WS_ - 1);
            #pragma unroll
            for (int u = 0; u < WS_; u++) {
                int kj = ch * WS_ + u;
                const float4* kk = (const float4*)&ks[kj * HD_];
                float dsum = 0.f;
                #pragma unroll
                for (int t = 0; t < 8; t++) {
                    float4 kv = kk[t];
                    dsum += q[t].x * kv.x + q[t].y * kv.y + q[t].z * kv.z + q[t].w * kv.w;
                }
                float msk = (lab[kj] != lq) ? -100.f : 0.f;
                sc[u] = dsum * scale + stable[rowoff + (j1 - u + WS_ - 1)] + msk;
                cmax = fmaxf(cmax, sc[u]);
            }
            float nm = fmaxf(m, cmax);
            float corr = __expf(m - nm);
            ssum *= corr;
            #pragma unroll
            for (int t = 0; t < 8; t++) {
                acc[t].x *= corr; acc[t].y *= corr; acc[t].z *= corr; acc[t].w *= corr;
            }
            #pragma unroll
            for (int u = 0; u < WS_; u++) {
                float p = __expf(sc[u] - nm);
                ssum += p;
                const float4* vv = (const float4*)&vs[(ch * WS_ + u) * HD_];
                #pragma unroll
                for (int t = 0; t < 8; t++) {
                    float4 vb = vv[t];
                    acc[t].x += p * vb.x; acc[t].y += p * vb.y;
                    acc[t].z += p * vb.z; acc[t].w += p * vb.w;
                }
            }
            m = nm;
        }
        float inv = 1.f / ssum;
        float4* og = (float4*)(ctx + ((size_t)(w * L_ + tid)) * C_ + head * HD_);
        #pragma unroll
        for (int t = 0; t < 8; t++) {
            float4 o;
            o.x = acc[t].x * inv; o.y = acc[t].y * inv;
            o.z = acc[t].z * inv; o.w = acc[t].w * inv;
            og[t] = o;
        }
    }
}

// ---------------- window reverse + un-shift + residual ----------------------
__global__ __launch_bounds__(256) void reverse_residual_kernel(
    const float* __restrict__ hidden, const float* __restrict__ att,
    float* __restrict__ hs)
{
    size_t idx = (size_t)blockIdx.x * 256 + threadIdx.x;
    int t = (int)(idx >> 9);
    int c = (int)(idx & 511);
    int b = t / (H_ * W_), p = t % (H_ * W_);
    int h = p / W_, w = p % W_;
    int hp = (h + H_ - SHIFT_) % H_;
    int wp = (w + W_ - SHIFT_) % W_;
    int wh = hp / WS_, i = hp % WS_, ww = wp / WS_, j = wp % WS_;
    int src = (b * NW_ + wh * NWW_ + ww) * L_ + i * WS_ + j;
    hs[idx] = hidden[idx] + att[(size_t)src * C_ + c];
}

// ---------------- driver ----------------------------------------------------
extern "C" void kernel_launch(void* const* d_in, const int* in_sizes, int n_in,
                              void* d_out, int out_size)
{
    const float* hidden = (const float*)d_in[0];
    const float* ln1_g  = (const float*)d_in[1];
    const float* ln1_b  = (const float*)d_in[2];
    const float* wq = (const float*)d_in[3];
    const float* bq = (const float*)d_in[4];
    const float* wk = (const float*)d_in[5];
    const float* bk = (const float*)d_in[6];
    const float* wv = (const float*)d_in[7];
    const float* bv = (const float*)d_in[8];
    const float* wo = (const float*)d_in[9];
    const float* bo = (const float*)d_in[10];
    const float* table = (const float*)d_in[11];
    const float* ln2_g = (const float*)d_in[12];
    const float* ln2_b = (const float*)d_in[13];
    const float* w1 = (const float*)d_in[14];
    const float* b1 = (const float*)d_in[15];
    const float* w2 = (const float*)d_in[16];
    const float* b2 = (const float*)d_in[17];
    float* out = (float*)d_out;

    float *pa, *pq, *pk, *pv, *pc, *phs, *pf;
    cudaGetSymbolAddress((void**)&pa,  g_a);
    cudaGetSymbolAddress((void**)&pq,  g_q);
    cudaGetSymbolAddress((void**)&pk,  g_k);
    cudaGetSymbolAddress((void**)&pv,  g_v);
    cudaGetSymbolAddress((void**)&pc,  g_c);
    cudaGetSymbolAddress((void**)&phs, g_hs);
    cudaGetSymbolAddress((void**)&pf,  g_f);

    const int GSMEM = 3 * STG_F * 4;  // 107520 bytes
    cudaFuncSetAttribute(gemm_mma, cudaFuncAttributeMaxDynamicSharedMemorySize, GSMEM);

    // 1) LN1 + shift + window partition -> g_a
    ln_kernel<<<TOK_, 128>>>(hidden, ln1_g, ln1_b, pa, 1);

    // 2) QKV projections
    dim3 gp(TOK_ / BM, C_ / BN);
    gemm_mma<<<gp, 256, GSMEM>>>(pa, wq, bq, nullptr, pq, C_, C_, 0);
    gemm_mma<<<gp, 256, GSMEM>>>(pa, wk, bk, nullptr, pk, C_, C_, 0);
    gemm_mma<<<gp, 256, GSMEM>>>(pa, wv, bv, nullptr, pv, C_, C_, 0);

    // 3) windowed attention -> g_c
    attn_kernel<<<dim3(B_ * NW_, NH_), 128>>>(pq, pk, pv, table, pc);

    // 4) output projection -> g_a
    gemm_mma<<<gp, 256, GSMEM>>>(pc, wo, bo, nullptr, pa, C_, C_, 0);

    // 5) window reverse + un-shift + residual -> g_hs
    reverse_residual_kernel<<<(TOK_ * C_) / 256, 256>>>(hidden, pa, phs);

    // 6) LN2 -> g_a
    ln_kernel<<<TOK_, 128>>>(phs, ln2_g, ln2_b, pa, 0);

    // 7) FFN1 + GELU -> g_f
    gemm_mma<<<dim3(TOK_ / BM, FF_ / BN), 256, GSMEM>>>(pa, w1, b1, nullptr, pf, FF_, C_, 1);

    // 8) FFN2 + residual -> out
    gemm_mma<<<gp, 256, GSMEM>>>(pf, w2, b2, phs, out, C_, FF_, 2);
}

// round 5
// speedup vs baseline: 3.7491x; 1.0317x over previous
#include <cuda_runtime.h>
#include <cuda_bf16.h>
#include <math.h>
#include <stdint.h>

// ---------------- static config ----------------
#define B_   8
#define H_   80
#define W_   60
#define C_   512
#define WS_  10
#define SHIFT_ 5
#define NH_  16
#define HD_  32
#define L_   100
#define NWH_ 8
#define NWW_ 6
#define NW_  48
#define TOK_ (B_*H_*W_)    // 38400
#define FF_  2048

// ---------------- scratch ----------------
__device__ float g_a [(size_t)TOK_*C_];
__device__ float g_q [(size_t)TOK_*C_];
__device__ float g_k [(size_t)TOK_*C_];
__device__ float g_v [(size_t)TOK_*C_];
__device__ float g_c [(size_t)TOK_*C_];
__device__ float g_hs[(size_t)TOK_*C_];
__device__ float g_f [(size_t)TOK_*FF_];

// ---------------- helpers ----------------
__device__ __forceinline__ uint32_t smem_u32(const void* p) {
    uint32_t a;
    asm("{ .reg .u64 t; cvta.to.shared.u64 t, %1; cvt.u32.u64 %0, t; }" : "=r"(a) : "l"(p));
    return a;
}
__device__ __forceinline__ void cp16(uint32_t s, const void* g) {
    asm volatile("cp.async.cg.shared.global [%0], [%1], 16;" :: "r"(s), "l"(g) : "memory");
}
__device__ __forceinline__ void mma_tf32(float* d, const float* a, const float* b) {
    const uint32_t* A = reinterpret_cast<const uint32_t*>(a);
    const uint32_t* B = reinterpret_cast<const uint32_t*>(b);
    asm volatile(
        "mma.sync.aligned.m16n8k8.row.col.f32.tf32.tf32.f32 "
        "{%0,%1,%2,%3}, {%4,%5,%6,%7}, {%8,%9}, {%0,%1,%2,%3};"
        : "+f"(d[0]), "+f"(d[1]), "+f"(d[2]), "+f"(d[3])
        : "r"(A[0]), "r"(A[1]), "r"(A[2]), "r"(A[3]), "r"(B[0]), "r"(B[1]));
}

// ---------------- block reduction for LN ----------------
__device__ __forceinline__ float block_sum_128(float v) {
    #pragma unroll
    for (int o = 16; o > 0; o >>= 1) v += __shfl_xor_sync(0xffffffffu, v, o);
    __shared__ float sh[4];
    int lane = threadIdx.x & 31, wid = threadIdx.x >> 5;
    __syncthreads();
    if (lane == 0) sh[wid] = v;
    __syncthreads();
    return sh[0] + sh[1] + sh[2] + sh[3];
}

// ---------------- LN1 fused with shift + window partition -------------------
__global__ __launch_bounds__(128) void ln_kernel(
    const float* __restrict__ x, const float* __restrict__ g,
    const float* __restrict__ bt, float* __restrict__ out)
{
    int r = blockIdx.x;
    int wg = r / L_, l = r % L_;
    int b = wg / NW_, wi = wg % NW_;
    int wh = wi / NWW_, ww = wi % NWW_;
    int h = (wh * WS_ + l / WS_ + SHIFT_) % H_;
    int w = (ww * WS_ + l % WS_ + SHIFT_) % W_;
    size_t in_row = (size_t)b * (H_ * W_) + h * W_ + w;

    const float* row = x + in_row * C_;
    float v[4]; float s = 0.f;
    #pragma unroll
    for (int e = 0; e < 4; e++) { v[e] = row[threadIdx.x + e * 128]; s += v[e]; }
    float mean = block_sum_128(s) * (1.f / C_);
    float d2 = 0.f;
    #pragma unroll
    for (int e = 0; e < 4; e++) { float d = v[e] - mean; d2 += d * d; }
    float var = block_sum_128(d2) * (1.f / C_);
    float rstd = rsqrtf(var + 1e-5f);
    float* o = out + (size_t)r * C_;
    #pragma unroll
    for (int e = 0; e < 4; e++) {
        int c = threadIdx.x + e * 128;
        o[c] = (v[e] - mean) * rstd * g[c] + bt[c];
    }
}

// ---- fused window-reverse + un-shift + residual + LN2 ----------------------
// one block per output token; writes hs (residual) AND ln2(hs)
__global__ __launch_bounds__(128) void rev_res_ln_kernel(
    const float* __restrict__ hidden, const float* __restrict__ att,
    const float* __restrict__ g, const float* __restrict__ bt,
    float* __restrict__ hs, float* __restrict__ lnout)
{
    int t = blockIdx.x;
    int b = t / (H_ * W_), p = t % (H_ * W_);
    int h = p / W_, w = p % W_;
    int hp = (h + H_ - SHIFT_) % H_;
    int wp = (w + W_ - SHIFT_) % W_;
    int src = (b * NW_ + (hp / WS_) * NWW_ + wp / WS_) * L_ + (hp % WS_) * WS_ + (wp % WS_);

    const float* hr = hidden + (size_t)t * C_;
    const float* ar = att + (size_t)src * C_;
    float* hsr = hs + (size_t)t * C_;
    float* lor = lnout + (size_t)t * C_;

    float v[4]; float s = 0.f;
    #pragma unroll
    for (int e = 0; e < 4; e++) {
        int c = threadIdx.x + e * 128;
        v[e] = hr[c] + ar[c];
        hsr[c] = v[e];
        s += v[e];
    }
    float mean = block_sum_128(s) * (1.f / C_);
    float d2 = 0.f;
    #pragma unroll
    for (int e = 0; e < 4; e++) { float d = v[e] - mean; d2 += d * d; }
    float var = block_sum_128(d2) * (1.f / C_);
    float rstd = rsqrtf(var + 1e-5f);
    #pragma unroll
    for (int e = 0; e < 4; e++) {
        int c = threadIdx.x + e * 128;
        lor[c] = (v[e] - mean) * rstd * g[c] + bt[c];
    }
}

// ---------------- tf32 mma.sync GEMM (3-stage, 1 barrier/chunk) -------------
#define BM 128
#define BN 128
#define BK 32
#define AST 36
#define BST 136
#define STG_F (BM * AST + BK * BST)   // floats per stage: 8960

__global__ __launch_bounds__(256, 2) void gemm_mma(
    const float* __restrict__ Act, const float* __restrict__ Wt,
    const float* __restrict__ bias, const float* __restrict__ res,
    float* __restrict__ out, int Nout, int K, int epi)
{
    extern __shared__ float sm[];

    int tid = threadIdx.x, lane = tid & 31, wid = tid >> 5;
    int tok0 = blockIdx.x * BM, n0 = blockIdx.y * BN;
    int wm0 = (wid & 1) * 64, wn0 = (wid >> 1) * 32;

    int a_row = tid >> 3, a_seg = tid & 7;
    int b_row = tid >> 5, b_seg = tid & 31;
    const float* a_gp = Act + (size_t)(tok0 + a_row) * K + a_seg * 4;
    const float* b_gp = Wt + (size_t)b_row * Nout + n0 + b_seg * 4;

    float acc[4][4][4];
    #pragma unroll
    for (int mt = 0; mt < 4; mt++)
        #pragma unroll
        for (int nt = 0; nt < 4; nt++)
            #pragma unroll
            for (int e = 0; e < 4; e++) acc[mt][nt][e] = 0.f;

    const int nch = K / BK;

    auto issue = [&](int c) {
        int s = c % 3;
        float* Ab = sm + s * STG_F;
        float* Bb = Ab + BM * AST;
        int k0 = c * BK;
        #pragma unroll
        for (int i = 0; i < 4; i++)
            cp16(smem_u32(Ab + (a_row + i * 32) * AST + a_seg * 4),
                 a_gp + (size_t)(i * 32) * K + k0);
        #pragma unroll
        for (int i = 0; i < 4; i++)
            cp16(smem_u32(Bb + (b_row + i * 8) * BST + b_seg * 4),
                 b_gp + (size_t)(k0 + i * 8) * Nout);
        asm volatile("cp.async.commit_group;" ::: "memory");
    };

    issue(0);
    issue(1);

    for (int c = 0; c < nch; c++) {
        if (c < nch - 1) {
            asm volatile("cp.async.wait_group 1;" ::: "memory");
        } else {
            asm volatile("cp.async.wait_group 0;" ::: "memory");
        }
        __syncthreads();
        if (c + 2 < nch) issue(c + 2);

        int s = c % 3;
        const float* A = sm + s * STG_F;
        const float* Bm = A + BM * AST;
        #pragma unroll
        for (int ks = 0; ks < 4; ks++) {
            float a[4][4], b[4][2];
            int arow = lane >> 2, acol = ks * 8 + (lane & 3);
            #pragma unroll
            for (int mt = 0; mt < 4; mt++) {
                int r = wm0 + mt * 16 + arow;
                a[mt][0] = A[r * AST + acol];
                a[mt][1] = A[(r + 8) * AST + acol];
                a[mt][2] = A[r * AST + acol + 4];
                a[mt][3] = A[(r + 8) * AST + acol + 4];
            }
            int brow0 = (ks * 8 + (lane & 3)) * BST;
            int brow1 = (ks * 8 + 4 + (lane & 3)) * BST;
            #pragma unroll
            for (int nt = 0; nt < 4; nt++) {
                int cn = wn0 + nt * 8 + (lane >> 2);
                b[nt][0] = Bm[brow0 + cn];
                b[nt][1] = Bm[brow1 + cn];
            }
            #pragma unroll
            for (int mt = 0; mt < 4; mt++)
                #pragma unroll
                for (int nt = 0; nt < 4; nt++)
                    mma_tf32(acc[mt][nt], a[mt], b[nt]);
        }
    }

    // ---- epilogue ----
    #pragma unroll
    for (int mt = 0; mt < 4; mt++) {
        #pragma unroll
        for (int nt = 0; nt < 4; nt++) {
            int r0 = tok0 + wm0 + mt * 16 + (lane >> 2);
            int c0 = n0 + wn0 + nt * 8 + 2 * (lane & 3);
            float2 bv = *(const float2*)(bias + c0);
            #pragma unroll
            for (int h = 0; h < 2; h++) {
                int row = r0 + h * 8;
                float v0 = acc[mt][nt][2 * h + 0] + bv.x;
                float v1 = acc[mt][nt][2 * h + 1] + bv.y;
                if (epi == 1) {
                    v0 = 0.5f * v0 * (1.f + erff(v0 * 0.70710678118654752f));
                    v1 = 0.5f * v1 * (1.f + erff(v1 * 0.70710678118654752f));
                } else if (epi == 2) {
                    float2 rr = *(const float2*)(res + (size_t)row * Nout + c0);
                    v0 += rr.x; v1 += rr.y;
                }
                float2 o; o.x = v0; o.y = v1;
                *(float2*)(out + (size_t)row * Nout + c0) = o;
            }
        }
    }
}

// ---------------- windowed attention (online softmax, q in regs) ------------
__global__ __launch_bounds__(128) void attn_kernel(
    const float* __restrict__ Q, const float* __restrict__ K,
    const float* __restrict__ V, const float* __restrict__ table,
    float* __restrict__ ctx)
{
    int w = blockIdx.x;
    int head = blockIdx.y;
    int wi = w % NW_;
    int wh = wi / NWW_, ww = wi % NWW_;

    __shared__ float ks[L_ * HD_];
    __shared__ float vs[L_ * HD_];
    __shared__ float stable[(2 * WS_ - 1) * (2 * WS_ - 1)];
    __shared__ int   lab[L_];

    int tid = threadIdx.x;
    for (int idx = tid; idx < L_ * HD_; idx += 128) {
        int l = idx >> 5, d = idx & 31;
        size_t gi = ((size_t)(w * L_ + l)) * C_ + head * HD_ + d;
        ks[idx] = K[gi];
        vs[idx] = V[gi];
    }
    for (int idx = tid; idx < 361; idx += 128) stable[idx] = table[idx * NH_ + head];
    if (tid < L_) {
        int i = tid / WS_, j = tid % WS_;
        int h = wh * WS_ + i, x = ww * WS_ + j;
        int rh = (h < H_ - WS_) ? 0 : ((h < H_ - SHIFT_) ? 1 : 2);
        int rw = (x < W_ - WS_) ? 0 : ((x < W_ - SHIFT_) ? 1 : 2);
        lab[tid] = rh * 3 + rw;
    }
    __syncthreads();

    if (tid < L_) {
        const float scale = 0.17677669529663687f;
        int i1 = tid / WS_, j1 = tid % WS_;
        int lq = lab[tid];
        float4 q[8];
        const float4* qg = (const float4*)(Q + ((size_t)(w * L_ + tid)) * C_ + head * HD_);
        #pragma unroll
        for (int t = 0; t < 8; t++) q[t] = qg[t];

        float m = -1e30f, ssum = 0.f;
        float4 acc[8];
        #pragma unroll
        for (int t = 0; t < 8; t++) acc[t] = make_float4(0.f, 0.f, 0.f, 0.f);

        for (int ch = 0; ch < WS_; ch++) {
            float sc[WS_];
            float cmax = -1e30f;
            int rowoff = (i1 - ch + WS_ - 1) * (2 * WS_ - 1);
            #pragma unroll
            for (int u = 0; u < WS_; u++) {
                int kj = ch * WS_ + u;
                const float4* kk = (const float4*)&ks[kj * HD_];
                float dsum = 0.f;
                #pragma unroll
                for (int t = 0; t < 8; t++) {
                    float4 kv = kk[t];
                    dsum += q[t].x * kv.x + q[t].y * kv.y + q[t].z * kv.z + q[t].w * kv.w;
                }
                float msk = (lab[kj] != lq) ? -100.f : 0.f;
                sc[u] = dsum * scale + stable[rowoff + (j1 - u + WS_ - 1)] + msk;
                cmax = fmaxf(cmax, sc[u]);
            }
            float nm = fmaxf(m, cmax);
            float corr = __expf(m - nm);
            ssum *= corr;
            #pragma unroll
            for (int t = 0; t < 8; t++) {
                acc[t].x *= corr; acc[t].y *= corr; acc[t].z *= corr; acc[t].w *= corr;
            }
            #pragma unroll
            for (int u = 0; u < WS_; u++) {
                float p = __expf(sc[u] - nm);
                ssum += p;
                const float4* vv = (const float4*)&vs[(ch * WS_ + u) * HD_];
                #pragma unroll
                for (int t = 0; t < 8; t++) {
                    float4 vb = vv[t];
                    acc[t].x += p * vb.x; acc[t].y += p * vb.y;
                    acc[t].z += p * vb.z; acc[t].w += p * vb.w;
                }
            }
            m = nm;
        }
        float inv = 1.f / ssum;
        float4* og = (float4*)(ctx + ((size_t)(w * L_ + tid)) * C_ + head * HD_);
        #pragma unroll
        for (int t = 0; t < 8; t++) {
            float4 o;
            o.x = acc[t].x * inv; o.y = acc[t].y * inv;
            o.z = acc[t].z * inv; o.w = acc[t].w * inv;
            og[t] = o;
        }
    }
}

// ---------------- driver ----------------------------------------------------
extern "C" void kernel_launch(void* const* d_in, const int* in_sizes, int n_in,
                              void* d_out, int out_size)
{
    const float* hidden = (const float*)d_in[0];
    const float* ln1_g  = (const float*)d_in[1];
    const float* ln1_b  = (const float*)d_in[2];
    const float* wq = (const float*)d_in[3];
    const float* bq = (const float*)d_in[4];
    const float* wk = (const float*)d_in[5];
    const float* bk = (const float*)d_in[6];
    const float* wv = (const float*)d_in[7];
    const float* bv = (const float*)d_in[8];
    const float* wo = (const float*)d_in[9];
    const float* bo = (const float*)d_in[10];
    const float* table = (const float*)d_in[11];
    const float* ln2_g = (const float*)d_in[12];
    const float* ln2_b = (const float*)d_in[13];
    const float* w1 = (const float*)d_in[14];
    const float* b1 = (const float*)d_in[15];
    const float* w2 = (const float*)d_in[16];
    const float* b2 = (const float*)d_in[17];
    float* out = (float*)d_out;

    float *pa, *pq, *pk, *pv, *pc, *phs, *pf;
    cudaGetSymbolAddress((void**)&pa,  g_a);
    cudaGetSymbolAddress((void**)&pq,  g_q);
    cudaGetSymbolAddress((void**)&pk,  g_k);
    cudaGetSymbolAddress((void**)&pv,  g_v);
    cudaGetSymbolAddress((void**)&pc,  g_c);
    cudaGetSymbolAddress((void**)&phs, g_hs);
    cudaGetSymbolAddress((void**)&pf,  g_f);

    const int GSMEM = 3 * STG_F * 4;  // 107520 bytes
    cudaFuncSetAttribute(gemm_mma, cudaFuncAttributeMaxDynamicSharedMemorySize, GSMEM);

    // 1) LN1 + shift + window partition -> g_a
    ln_kernel<<<TOK_, 128>>>(hidden, ln1_g, ln1_b, pa);

    // 2) QKV projections
    dim3 gp(TOK_ / BM, C_ / BN);
    gemm_mma<<<gp, 256, GSMEM>>>(pa, wq, bq, nullptr, pq, C_, C_, 0);
    gemm_mma<<<gp, 256, GSMEM>>>(pa, wk, bk, nullptr, pk, C_, C_, 0);
    gemm_mma<<<gp, 256, GSMEM>>>(pa, wv, bv, nullptr, pv, C_, C_, 0);

    // 3) windowed attention -> g_c
    attn_kernel<<<dim3(B_ * NW_, NH_), 128>>>(pq, pk, pv, table, pc);

    // 4) output projection -> g_a
    gemm_mma<<<gp, 256, GSMEM>>>(pc, wo, bo, nullptr, pa, C_, C_, 0);

    // 5) window reverse + un-shift + residual + LN2 -> g_hs, g_q (reuse as LN2 out)
    rev_res_ln_kernel<<<TOK_, 128>>>(hidden, pa, ln2_g, ln2_b, phs, pq);

    // 6) FFN1 + GELU -> g_f
    gemm_mma<<<dim3(TOK_ / BM, FF_ / BN), 256, GSMEM>>>(pq, w1, b1, nullptr, pf, FF_, C_, 1);

    // 7) FFN2 + residual -> out
    gemm_mma<<<gp, 256, GSMEM>>>(pf, w2, b2, phs, out, C_, FF_, 2);
}

// round 7
// speedup vs baseline: 3.8606x; 1.0297x over previous
#include <cuda_runtime.h>
#include <cuda_bf16.h>
#include <math.h>
#include <stdint.h>

// ---------------- static config ----------------
#define B_   8
#define H_   80
#define W_   60
#define C_   512
#define WS_  10
#define SHIFT_ 5
#define NH_  16
#define HD_  32
#define L_   100
#define NWH_ 8
#define NWW_ 6
#define NW_  48
#define TOK_ (B_*H_*W_)    // 38400
#define FF_  2048

// ---------------- scratch ----------------
__device__ float g_a [(size_t)TOK_*C_];
__device__ float g_q [(size_t)TOK_*C_];
__device__ float g_k [(size_t)TOK_*C_];
__device__ float g_v [(size_t)TOK_*C_];
__device__ float g_c [(size_t)TOK_*C_];
__device__ float g_hs[(size_t)TOK_*C_];
__device__ float g_f [(size_t)TOK_*FF_];

// ---------------- helpers ----------------
__device__ __forceinline__ uint32_t smem_u32(const void* p) {
    uint32_t a;
    asm("{ .reg .u64 t; cvta.to.shared.u64 t, %1; cvt.u32.u64 %0, t; }" : "=r"(a) : "l"(p));
    return a;
}
__device__ __forceinline__ void cp16(uint32_t s, const void* g) {
    asm volatile("cp.async.cg.shared.global [%0], [%1], 16;" :: "r"(s), "l"(g) : "memory");
}
__device__ __forceinline__ void mma_tf32(float* d, const float* a, const float* b) {
    const uint32_t* A = reinterpret_cast<const uint32_t*>(a);
    const uint32_t* B = reinterpret_cast<const uint32_t*>(b);
    asm volatile(
        "mma.sync.aligned.m16n8k8.row.col.f32.tf32.tf32.f32 "
        "{%0,%1,%2,%3}, {%4,%5,%6,%7}, {%8,%9}, {%0,%1,%2,%3};"
        : "+f"(d[0]), "+f"(d[1]), "+f"(d[2]), "+f"(d[3])
        : "r"(A[0]), "r"(A[1]), "r"(A[2]), "r"(A[3]), "r"(B[0]), "r"(B[1]));
}

// ---------------- block reduction for LN ----------------
__device__ __forceinline__ float block_sum_128(float v) {
    #pragma unroll
    for (int o = 16; o > 0; o >>= 1) v += __shfl_xor_sync(0xffffffffu, v, o);
    __shared__ float sh[4];
    int lane = threadIdx.x & 31, wid = threadIdx.x >> 5;
    __syncthreads();
    if (lane == 0) sh[wid] = v;
    __syncthreads();
    return sh[0] + sh[1] + sh[2] + sh[3];
}

// ---------------- LN1 fused with shift + window partition -------------------
__global__ __launch_bounds__(128) void ln_kernel(
    const float* __restrict__ x, const float* __restrict__ g,
    const float* __restrict__ bt, float* __restrict__ out)
{
    int r = blockIdx.x;
    int wg = r / L_, l = r % L_;
    int b = wg / NW_, wi = wg % NW_;
    int wh = wi / NWW_, ww = wi % NWW_;
    int h = (wh * WS_ + l / WS_ + SHIFT_) % H_;
    int w = (ww * WS_ + l % WS_ + SHIFT_) % W_;
    size_t in_row = (size_t)b * (H_ * W_) + h * W_ + w;

    const float* row = x + in_row * C_;
    float v[4]; float s = 0.f;
    #pragma unroll
    for (int e = 0; e < 4; e++) { v[e] = row[threadIdx.x + e * 128]; s += v[e]; }
    float mean = block_sum_128(s) * (1.f / C_);
    float d2 = 0.f;
    #pragma unroll
    for (int e = 0; e < 4; e++) { float d = v[e] - mean; d2 += d * d; }
    float var = block_sum_128(d2) * (1.f / C_);
    float rstd = rsqrtf(var + 1e-5f);
    float* o = out + (size_t)r * C_;
    #pragma unroll
    for (int e = 0; e < 4; e++) {
        int c = threadIdx.x + e * 128;
        o[c] = (v[e] - mean) * rstd * g[c] + bt[c];
    }
}

// ---- fused window-reverse + un-shift + residual + LN2 ----------------------
__global__ __launch_bounds__(128) void rev_res_ln_kernel(
    const float* __restrict__ hidden, const float* __restrict__ att,
    const float* __restrict__ g, const float* __restrict__ bt,
    float* __restrict__ hs, float* __restrict__ lnout)
{
    int t = blockIdx.x;
    int b = t / (H_ * W_), p = t % (H_ * W_);
    int h = p / W_, w = p % W_;
    int hp = (h + H_ - SHIFT_) % H_;
    int wp = (w + W_ - SHIFT_) % W_;
    int src = (b * NW_ + (hp / WS_) * NWW_ + wp / WS_) * L_ + (hp % WS_) * WS_ + (wp % WS_);

    const float* hr = hidden + (size_t)t * C_;
    const float* ar = att + (size_t)src * C_;
    float* hsr = hs + (size_t)t * C_;
    float* lor = lnout + (size_t)t * C_;

    float v[4]; float s = 0.f;
    #pragma unroll
    for (int e = 0; e < 4; e++) {
        int c = threadIdx.x + e * 128;
        v[e] = hr[c] + ar[c];
        hsr[c] = v[e];
        s += v[e];
    }
    float mean = block_sum_128(s) * (1.f / C_);
    float d2 = 0.f;
    #pragma unroll
    for (int e = 0; e < 4; e++) { float d = v[e] - mean; d2 += d * d; }
    float var = block_sum_128(d2) * (1.f / C_);
    float rstd = rsqrtf(var + 1e-5f);
    #pragma unroll
    for (int e = 0; e < 4; e++) {
        int c = threadIdx.x + e * 128;
        lor[c] = (v[e] - mean) * rstd * g[c] + bt[c];
    }
}

// ---------------- tf32 mma.sync GEMM (128 thr, warp tile 64x64) -------------
#define BM 128
#define BN 128
#define BK 32
#define AST 36
#define BST 136
#define STG_F (BM * AST + BK * BST)   // 8960 floats / stage

__global__ __launch_bounds__(128, 2) void gemm_mma(
    const float* __restrict__ Act, const float* __restrict__ Wt,
    const float* __restrict__ bias, const float* __restrict__ res,
    float* __restrict__ out, int Nout, int K, int epi)
{
    extern __shared__ float sm[];

    int tid = threadIdx.x, lane = tid & 31, wid = tid >> 5;
    int tok0 = blockIdx.x * BM, n0 = blockIdx.y * BN;
    int wm0 = (wid & 1) * 64, wn0 = (wid >> 1) * 64;

    int a_row = tid >> 3, a_seg = tid & 7;      // + i*16 rows (8 iters)
    int b_row = tid >> 5, b_seg = tid & 31;     // + i*4 rows (8 iters)
    const float* a_gp = Act + (size_t)(tok0 + a_row) * K + a_seg * 4;
    const float* b_gp = Wt + (size_t)b_row * Nout + n0 + b_seg * 4;

    float acc[4][8][4];
    #pragma unroll
    for (int mt = 0; mt < 4; mt++)
        #pragma unroll
        for (int nt = 0; nt < 8; nt++)
            #pragma unroll
            for (int e = 0; e < 4; e++) acc[mt][nt][e] = 0.f;

    const int nch = K / BK;

    auto issue = [&](int c) {
        int s = c % 3;
        float* Ab = sm + s * STG_F;
        float* Bb = Ab + BM * AST;
        int k0 = c * BK;
        #pragma unroll
        for (int i = 0; i < 8; i++)
            cp16(smem_u32(Ab + (a_row + i * 16) * AST + a_seg * 4),
                 a_gp + (size_t)(i * 16) * K + k0);
        #pragma unroll
        for (int i = 0; i < 8; i++)
            cp16(smem_u32(Bb + (b_row + i * 4) * BST + b_seg * 4),
                 b_gp + (size_t)(k0 + i * 4) * Nout);
        asm volatile("cp.async.commit_group;" ::: "memory");
    };

    issue(0);
    issue(1);

    for (int c = 0; c < nch; c++) {
        if (c < nch - 1) {
            asm volatile("cp.async.wait_group 1;" ::: "memory");
        } else {
            asm volatile("cp.async.wait_group 0;" ::: "memory");
        }
        __syncthreads();
        if (c + 2 < nch) issue(c + 2);

        int s = c % 3;
        const float* A = sm + s * STG_F;
        const float* Bm = A + BM * AST;
        #pragma unroll
        for (int ks = 0; ks < 4; ks++) {
            float a[4][4], b[8][2];
            int arow = lane >> 2, acol = ks * 8 + (lane & 3);
            #pragma unroll
            for (int mt = 0; mt < 4; mt++) {
                int r = wm0 + mt * 16 + arow;
                a[mt][0] = A[r * AST + acol];
                a[mt][1] = A[(r + 8) * AST + acol];
                a[mt][2] = A[r * AST + acol + 4];
                a[mt][3] = A[(r + 8) * AST + acol + 4];
            }
            int brow0 = (ks * 8 + (lane & 3)) * BST;
            int brow1 = (ks * 8 + 4 + (lane & 3)) * BST;
            #pragma unroll
            for (int nt = 0; nt < 8; nt++) {
                int cn = wn0 + nt * 8 + (lane >> 2);
                b[nt][0] = Bm[brow0 + cn];
                b[nt][1] = Bm[brow1 + cn];
            }
            #pragma unroll
            for (int mt = 0; mt < 4; mt++)
                #pragma unroll
                for (int nt = 0; nt < 8; nt++)
                    mma_tf32(acc[mt][nt], a[mt], b[nt]);
        }
    }

    // ---- epilogue ----
    #pragma unroll
    for (int mt = 0; mt < 4; mt++) {
        #pragma unroll
        for (int nt = 0; nt < 8; nt++) {
            int r0 = tok0 + wm0 + mt * 16 + (lane >> 2);
            int c0 = n0 + wn0 + nt * 8 + 2 * (lane & 3);
            float2 bv = *(const float2*)(bias + c0);
            #pragma unroll
            for (int h = 0; h < 2; h++) {
                int row = r0 + h * 8;
                float v0 = acc[mt][nt][2 * h + 0] + bv.x;
                float v1 = acc[mt][nt][2 * h + 1] + bv.y;
                if (epi == 1) {
                    v0 = 0.5f * v0 * (1.f + erff(v0 * 0.70710678118654752f));
                    v1 = 0.5f * v1 * (1.f + erff(v1 * 0.70710678118654752f));
                } else if (epi == 2) {
                    float2 rr = *(const float2*)(res + (size_t)row * Nout + c0);
                    v0 += rr.x; v1 += rr.y;
                }
                float2 o; o.x = v0; o.y = v1;
                *(float2*)(out + (size_t)row * Nout + c0) = o;
            }
        }
    }
}

// ---------------- windowed attention (online softmax, q in regs) ------------
__global__ __launch_bounds__(128) void attn_kernel(
    const float* __restrict__ Q, const float* __restrict__ K,
    const float* __restrict__ V, const float* __restrict__ table,
    float* __restrict__ ctx)
{
    int w = blockIdx.x;
    int head = blockIdx.y;
    int wi = w % NW_;
    int wh = wi / NWW_, ww = wi % NWW_;

    __shared__ float ks[L_ * HD_];
    __shared__ float vs[L_ * HD_];
    __shared__ float stable[(2 * WS_ - 1) * (2 * WS_ - 1)];
    __shared__ int   lab[L_];

    int tid = threadIdx.x;
    for (int idx = tid; idx < L_ * HD_; idx += 128) {
        int l = idx >> 5, d = idx & 31;
        size_t gi = ((size_t)(w * L_ + l)) * C_ + head * HD_ + d;
        ks[idx] = K[gi];
        vs[idx] = V[gi];
    }
    for (int idx = tid; idx < 361; idx += 128) stable[idx] = table[idx * NH_ + head];
    if (tid < L_) {
        int i = tid / WS_, j = tid % WS_;
        int h = wh * WS_ + i, x = ww * WS_ + j;
        int rh = (h < H_ - WS_) ? 0 : ((h < H_ - SHIFT_) ? 1 : 2);
        int rw = (x < W_ - WS_) ? 0 : ((x < W_ - SHIFT_) ? 1 : 2);
        lab[tid] = rh * 3 + rw;
    }
    __syncthreads();

    if (tid < L_) {
        const float scale = 0.17677669529663687f;
        int i1 = tid / WS_, j1 = tid % WS_;
        int lq = lab[tid];
        float4 q[8];
        const float4* qg = (const float4*)(Q + ((size_t)(w * L_ + tid)) * C_ + head * HD_);
        #pragma unroll
        for (int t = 0; t < 8; t++) q[t] = qg[t];

        float m = -1e30f, ssum = 0.f;
        float4 acc[8];
        #pragma unroll
        for (int t = 0; t < 8; t++) acc[t] = make_float4(0.f, 0.f, 0.f, 0.f);

        for (int ch = 0; ch < WS_; ch++) {
            float sc[WS_];
            float cmax = -1e30f;
            int rowoff = (i1 - ch + WS_ - 1) * (2 * WS_ - 1);
            #pragma unroll
            for (int u = 0; u < WS_; u++) {
                int kj = ch * WS_ + u;
                const float4* kk = (const float4*)&ks[kj * HD_];
                float dsum = 0.f;
                #pragma unroll
                for (int t = 0; t < 8; t++) {
                    float4 kv = kk[t];
                    dsum += q[t].x * kv.x + q[t].y * kv.y + q[t].z * kv.z + q[t].w * kv.w;
                }
                float msk = (lab[kj] != lq) ? -100.f : 0.f;
                sc[u] = dsum * scale + stable[rowoff + (j1 - u + WS_ - 1)] + msk;
                cmax = fmaxf(cmax, sc[u]);
            }
            float nm = fmaxf(m, cmax);
            float corr = __expf(m - nm);
            ssum *= corr;
            #pragma unroll
            for (int t = 0; t < 8; t++) {
                acc[t].x *= corr; acc[t].y *= corr; acc[t].z *= corr; acc[t].w *= corr;
            }
            #pragma unroll
            for (int u = 0; u < WS_; u++) {
                float p = __expf(sc[u] - nm);
                ssum += p;
                const float4* vv = (const float4*)&vs[(ch * WS_ + u) * HD_];
                #pragma unroll
                for (int t = 0; t < 8; t++) {
                    float4 vb = vv[t];
                    acc[t].x += p * vb.x; acc[t].y += p * vb.y;
                    acc[t].z += p * vb.z; acc[t].w += p * vb.w;
                }
            }
            m = nm;
        }
        float inv = 1.f / ssum;
        float4* og = (float4*)(ctx + ((size_t)(w * L_ + tid)) * C_ + head * HD_);
        #pragma unroll
        for (int t = 0; t < 8; t++) {
            float4 o;
            o.x = acc[t].x * inv; o.y = acc[t].y * inv;
            o.z = acc[t].z * inv; o.w = acc[t].w * inv;
            og[t] = o;
        }
    }
}

// ---------------- driver ----------------------------------------------------
extern "C" void kernel_launch(void* const* d_in, const int* in_sizes, int n_in,
                              void* d_out, int out_size)
{
    const float* hidden = (const float*)d_in[0];
    const float* ln1_g  = (const float*)d_in[1];
    const float* ln1_b  = (const float*)d_in[2];
    const float* wq = (const float*)d_in[3];
    const float* bq = (const float*)d_in[4];
    const float* wk = (const float*)d_in[5];
    const float* bk = (const float*)d_in[6];
    const float* wv = (const float*)d_in[7];
    const float* bv = (const float*)d_in[8];
    const float* wo = (const float*)d_in[9];
    const float* bo = (const float*)d_in[10];
    const float* table = (const float*)d_in[11];
    const float* ln2_g = (const float*)d_in[12];
    const float* ln2_b = (const float*)d_in[13];
    const float* w1 = (const float*)d_in[14];
    const float* b1 = (const float*)d_in[15];
    const float* w2 = (const float*)d_in[16];
    const float* b2 = (const float*)d_in[17];
    float* out = (float*)d_out;

    float *pa, *pq, *pk, *pv, *pc, *phs, *pf;
    cudaGetSymbolAddress((void**)&pa,  g_a);
    cudaGetSymbolAddress((void**)&pq,  g_q);
    cudaGetSymbolAddress((void**)&pk,  g_k);
    cudaGetSymbolAddress((void**)&pv,  g_v);
    cudaGetSymbolAddress((void**)&pc,  g_c);
    cudaGetSymbolAddress((void**)&phs, g_hs);
    cudaGetSymbolAddress((void**)&pf,  g_f);

    const int GSMEM = 3 * STG_F * 4;  // 107520 bytes
    cudaFuncSetAttribute(gemm_mma, cudaFuncAttributeMaxDynamicSharedMemorySize, GSMEM);

    // 1) LN1 + shift + window partition -> g_a
    ln_kernel<<<TOK_, 128>>>(hidden, ln1_g, ln1_b, pa);

    // 2) QKV projections
    dim3 gp(TOK_ / BM, C_ / BN);
    gemm_mma<<<gp, 128, GSMEM>>>(pa, wq, bq, nullptr, pq, C_, C_, 0);
    gemm_mma<<<gp, 128, GSMEM>>>(pa, wk, bk, nullptr, pk, C_, C_, 0);
    gemm_mma<<<gp, 128, GSMEM>>>(pa, wv, bv, nullptr, pv, C_, C_, 0);

    // 3) windowed attention -> g_c
    attn_kernel<<<dim3(B_ * NW_, NH_), 128>>>(pq, pk, pv, table, pc);

    // 4) output projection -> g_a
    gemm_mma<<<gp, 128, GSMEM>>>(pc, wo, bo, nullptr, pa, C_, C_, 0);

    // 5) window reverse + un-shift + residual + LN2 -> g_hs, g_q
    rev_res_ln_kernel<<<TOK_, 128>>>(hidden, pa, ln2_g, ln2_b, phs, pq);

    // 6) FFN1 + GELU -> g_f
    gemm_mma<<<dim3(TOK_ / BM, FF_ / BN), 128, GSMEM>>>(pq, w1, b1, nullptr, pf, FF_, C_, 1);

    // 7) FFN2 + residual -> out
    gemm_mma<<<gp, 128, GSMEM>>>(pf, w2, b2, phs, out, C_, FF_, 2);
}

// round 9
// speedup vs baseline: 5.3160x; 1.3770x over previous
#include <cuda_runtime.h>
#include <cuda_fp16.h>
#include <math.h>
#include <stdint.h>

// ---------------- static config ----------------
#define B_   8
#define H_   80
#define W_   60
#define C_   512
#define WS_  10
#define SHIFT_ 5
#define NH_  16
#define HD_  32
#define L_   100
#define NWH_ 8
#define NWW_ 6
#define NW_  48
#define TOK_ (B_*H_*W_)    // 38400
#define FF_  2048

// ---------------- scratch ----------------
__device__ __half g_ah[(size_t)TOK_*C_];     // half activations (LN1 out, later LN2 out)
__device__ float  g_q [(size_t)TOK_*C_];     // Q f32 (later out-proj out)
__device__ float  g_k [(size_t)TOK_*C_];
__device__ float  g_v [(size_t)TOK_*C_];
__device__ __half g_ch[(size_t)TOK_*C_];     // ctx half
__device__ float  g_hs[(size_t)TOK_*C_];     // residual
__device__ __half g_fh[(size_t)TOK_*FF_];    // FFN hidden half
__device__ __half g_wh[3145728];             // converted weights (pair-interleaved)

// ---------------- helpers ----------------
__device__ __forceinline__ uint32_t smem_u32(const void* p) {
    uint32_t a;
    asm("{ .reg .u64 t; cvta.to.shared.u64 t, %1; cvt.u32.u64 %0, t; }" : "=r"(a) : "l"(p));
    return a;
}
__device__ __forceinline__ void cp16(uint32_t s, const void* g) {
    asm volatile("cp.async.cg.shared.global [%0], [%1], 16;" :: "r"(s), "l"(g) : "memory");
}
__device__ __forceinline__ void mma_f16(float* d, const uint32_t* a, const uint32_t* b) {
    asm volatile(
        "mma.sync.aligned.m16n8k16.row.col.f32.f16.f16.f32 "
        "{%0,%1,%2,%3}, {%4,%5,%6,%7}, {%8,%9}, {%0,%1,%2,%3};"
        : "+f"(d[0]), "+f"(d[1]), "+f"(d[2]), "+f"(d[3])
        : "r"(a[0]), "r"(a[1]), "r"(a[2]), "r"(a[3]), "r"(b[0]), "r"(b[1]));
}

// ---------------- weight conversion: W[K][N] f32 -> Wh[K/2][N][2] half ------
__global__ __launch_bounds__(256) void convw_kernel(
    const float* __restrict__ w, __half* __restrict__ out, int K, int N)
{
    int idx = blockIdx.x * 256 + threadIdx.x;
    if (idx >= K * N) return;
    int k = idx / N, n = idx - k * N;
    out[(size_t)(k >> 1) * (2 * N) + 2 * n + (k & 1)] = __float2half(w[idx]);
}

// ---------------- block reduction for LN ----------------
__device__ __forceinline__ float block_sum_128(float v) {
    #pragma unroll
    for (int o = 16; o > 0; o >>= 1) v += __shfl_xor_sync(0xffffffffu, v, o);
    __shared__ float sh[4];
    int lane = threadIdx.x & 31, wid = threadIdx.x >> 5;
    __syncthreads();
    if (lane == 0) sh[wid] = v;
    __syncthreads();
    return sh[0] + sh[1] + sh[2] + sh[3];
}

// ---------------- LN1 + shift + window partition -> half --------------------
__global__ __launch_bounds__(128) void ln_kernel(
    const float* __restrict__ x, const float* __restrict__ g,
    const float* __restrict__ bt, __half* __restrict__ out)
{
    int r = blockIdx.x;
    int wg = r / L_, l = r % L_;
    int b = wg / NW_, wi = wg % NW_;
    int wh = wi / NWW_, ww = wi % NWW_;
    int h = (wh * WS_ + l / WS_ + SHIFT_) % H_;
    int w = (ww * WS_ + l % WS_ + SHIFT_) % W_;
    size_t in_row = (size_t)b * (H_ * W_) + h * W_ + w;

    const float* row = x + in_row * C_;
    float v[4]; float s = 0.f;
    #pragma unroll
    for (int e = 0; e < 4; e++) { v[e] = row[threadIdx.x + e * 128]; s += v[e]; }
    float mean = block_sum_128(s) * (1.f / C_);
    float d2 = 0.f;
    #pragma unroll
    for (int e = 0; e < 4; e++) { float d = v[e] - mean; d2 += d * d; }
    float var = block_sum_128(d2) * (1.f / C_);
    float rstd = rsqrtf(var + 1e-5f);
    __half* o = out + (size_t)r * C_;
    #pragma unroll
    for (int e = 0; e < 4; e++) {
        int c = threadIdx.x + e * 128;
        o[c] = __float2half((v[e] - mean) * rstd * g[c] + bt[c]);
    }
}

// ---- window-reverse + un-shift + residual + LN2 (ln out half) --------------
__global__ __launch_bounds__(128) void rev_res_ln_kernel(
    const float* __restrict__ hidden, const float* __restrict__ att,
    const float* __restrict__ g, const float* __restrict__ bt,
    float* __restrict__ hs, __half* __restrict__ lnout)
{
    int t = blockIdx.x;
    int b = t / (H_ * W_), p = t % (H_ * W_);
    int h = p / W_, w = p % W_;
    int hp = (h + H_ - SHIFT_) % H_;
    int wp = (w + W_ - SHIFT_) % W_;
    int src = (b * NW_ + (hp / WS_) * NWW_ + wp / WS_) * L_ + (hp % WS_) * WS_ + (wp % WS_);

    const float* hr = hidden + (size_t)t * C_;
    const float* ar = att + (size_t)src * C_;
    float* hsr = hs + (size_t)t * C_;
    __half* lor = lnout + (size_t)t * C_;

    float v[4]; float s = 0.f;
    #pragma unroll
    for (int e = 0; e < 4; e++) {
        int c = threadIdx.x + e * 128;
        v[e] = hr[c] + ar[c];
        hsr[c] = v[e];
        s += v[e];
    }
    float mean = block_sum_128(s) * (1.f / C_);
    float d2 = 0.f;
    #pragma unroll
    for (int e = 0; e < 4; e++) { float d = v[e] - mean; d2 += d * d; }
    float var = block_sum_128(d2) * (1.f / C_);
    float rstd = rsqrtf(var + 1e-5f);
    #pragma unroll
    for (int e = 0; e < 4; e++) {
        int c = threadIdx.x + e * 128;
        lor[c] = __float2half((v[e] - mean) * rstd * g[c] + bt[c]);
    }
}

// ---------------- fp16 mma.sync GEMM (256 thr, warp 64x32, 3-stage) ---------
// A: half [M][K] row-major.  W: half pair-interleaved [K/2][N][2].
// epi: 0 -> f32 out;  1 -> half out + GELU;  2 -> f32 out + res
#define BM 128
#define BN 128
#define BK 32
#define ASW 36                       // A stride (32-bit words) per row
#define BSW 136                      // B stride (words) per k-pair row
#define STG_W (BM * ASW + 16 * BSW)  // words/stage = 4608+2176 = 6784 (27136 B)

__global__ __launch_bounds__(256, 2) void gemm_h(
    const __half* __restrict__ Ah, const __half* __restrict__ Wh,
    const float* __restrict__ bias, const float* __restrict__ res,
    void* __restrict__ outp, int Nout, int K, int epi)
{
    extern __shared__ uint32_t sm[];

    int tid = threadIdx.x, lane = tid & 31, wid = tid >> 5;
    int tok0 = blockIdx.x * BM, n0 = blockIdx.y * BN;
    int wm0 = (wid & 1) * 64, wn0 = (wid >> 1) * 32;

    int a_row = tid >> 2, a_seg = tid & 3;       // +i*64 rows (2 iters)
    int b_row = tid >> 4, b_seg = tid & 15;      // +i*16 segs (2 iters)
    const __half* a_gp = Ah + (size_t)(tok0 + a_row) * K + a_seg * 8;
    const __half* b_gp = Wh + (size_t)b_row * (2 * Nout) + n0 * 2 + b_seg * 8;

    float acc[4][4][4];
    #pragma unroll
    for (int mt = 0; mt < 4; mt++)
        #pragma unroll
        for (int nt = 0; nt < 4; nt++)
            #pragma unroll
            for (int e = 0; e < 4; e++) acc[mt][nt][e] = 0.f;

    const int nch = K / BK;

    auto issue = [&](int c) {
        int s = c % 3;
        uint32_t* Ab = sm + s * STG_W;
        uint32_t* Bb = Ab + BM * ASW;
        int k0 = c * BK;
        #pragma unroll
        for (int i = 0; i < 2; i++)
            cp16(smem_u32(Ab + (a_row + i * 64) * ASW + a_seg * 4),
                 a_gp + (size_t)(i * 64) * K + k0);
        #pragma unroll
        for (int i = 0; i < 2; i++)
            cp16(smem_u32(Bb + b_row * BSW + (b_seg + i * 16) * 4),
                 b_gp + (size_t)(k0 >> 1) * (2 * Nout) + i * 128);
        asm volatile("cp.async.commit_group;" ::: "memory");
    };

    issue(0);
    issue(1);

    for (int c = 0; c < nch; c++) {
        if (c < nch - 1) {
            asm volatile("cp.async.wait_group 1;" ::: "memory");
        } else {
            asm volatile("cp.async.wait_group 0;" ::: "memory");
        }
        __syncthreads();
        if (c + 2 < nch) issue(c + 2);

        int s = c % 3;
        const uint32_t* A = sm + s * STG_W;
        const uint32_t* Bm = A + BM * ASW;
        int arow = lane >> 2, c4 = lane & 3, bn = lane >> 2;
        #pragma unroll
        for (int ks = 0; ks < 2; ks++) {
            uint32_t a[4][4], b[4][2];
            int acol = ks * 8 + c4;
            #pragma unroll
            for (int mt = 0; mt < 4; mt++) {
                int r = wm0 + mt * 16 + arow;
                a[mt][0] = A[r * ASW + acol];
                a[mt][1] = A[(r + 8) * ASW + acol];
                a[mt][2] = A[r * ASW + acol + 4];
                a[mt][3] = A[(r + 8) * ASW + acol + 4];
            }
            int pb0 = (ks * 8 + c4) * BSW;
            int pb1 = (ks * 8 + c4 + 4) * BSW;
            #pragma unroll
            for (int nt = 0; nt < 4; nt++) {
                int n = wn0 + nt * 8 + bn;
                b[nt][0] = Bm[pb0 + n];
                b[nt][1] = Bm[pb1 + n];
            }
            #pragma unroll
            for (int mt = 0; mt < 4; mt++)
                #pragma unroll
                for (int nt = 0; nt < 4; nt++)
                    mma_f16(acc[mt][nt], a[mt], b[nt]);
        }
    }

    // ---- epilogue ----
    #pragma unroll
    for (int mt = 0; mt < 4; mt++) {
        #pragma unroll
        for (int nt = 0; nt < 4; nt++) {
            int r0 = tok0 + wm0 + mt * 16 + (lane >> 2);
            int c0 = n0 + wn0 + nt * 8 + 2 * (lane & 3);
            float2 bv = *(const float2*)(bias + c0);
            #pragma unroll
            for (int h = 0; h < 2; h++) {
                int row = r0 + h * 8;
                float v0 = acc[mt][nt][2 * h + 0] + bv.x;
                float v1 = acc[mt][nt][2 * h + 1] + bv.y;
                if (epi == 1) {
                    v0 = 0.5f * v0 * (1.f + erff(v0 * 0.70710678118654752f));
                    v1 = 0.5f * v1 * (1.f + erff(v1 * 0.70710678118654752f));
                    *(__half2*)((__half*)outp + (size_t)row * Nout + c0) =
                        __floats2half2_rn(v0, v1);
                } else {
                    if (epi == 2) {
                        float2 rr = *(const float2*)(res + (size_t)row * Nout + c0);
                        v0 += rr.x; v1 += rr.y;
                    }
                    float2 o; o.x = v0; o.y = v1;
                    *(float2*)((float*)outp + (size_t)row * Nout + c0) = o;
                }
            }
        }
    }
}

// ---------------- windowed attention (f32 in, half ctx out) -----------------
__global__ __launch_bounds__(128) void attn_kernel(
    const float* __restrict__ Q, const float* __restrict__ K,
    const float* __restrict__ V, const float* __restrict__ table,
    __half* __restrict__ ctx)
{
    int w = blockIdx.x;
    int head = blockIdx.y;
    int wi = w % NW_;
    int wh = wi / NWW_, ww = wi % NWW_;

    __shared__ float ks[L_ * HD_];
    __shared__ float vs[L_ * HD_];
    __shared__ float stable[(2 * WS_ - 1) * (2 * WS_ - 1)];
    __shared__ int   lab[L_];

    int tid = threadIdx.x;
    for (int idx = tid; idx < L_ * HD_; idx += 128) {
        int l = idx >> 5, d = idx & 31;
        size_t gi = ((size_t)(w * L_ + l)) * C_ + head * HD_ + d;
        ks[idx] = K[gi];
        vs[idx] = V[gi];
    }
    for (int idx = tid; idx < 361; idx += 128) stable[idx] = table[idx * NH_ + head];
    if (tid < L_) {
        int i = tid / WS_, j = tid % WS_;
        int h = wh * WS_ + i, x = ww * WS_ + j;
        int rh = (h < H_ - WS_) ? 0 : ((h < H_ - SHIFT_) ? 1 : 2);
        int rw = (x < W_ - WS_) ? 0 : ((x < W_ - SHIFT_) ? 1 : 2);
        lab[tid] = rh * 3 + rw;
    }
    __syncthreads();

    if (tid < L_) {
        const float scale = 0.17677669529663687f;
        int i1 = tid / WS_, j1 = tid % WS_;
        int lq = lab[tid];
        float4 q[8];
        const float4* qg = (const float4*)(Q + ((size_t)(w * L_ + tid)) * C_ + head * HD_);
        #pragma unroll
        for (int t = 0; t < 8; t++) q[t] = qg[t];

        float m = -1e30f, ssum = 0.f;
        float4 acc[8];
        #pragma unroll
        for (int t = 0; t < 8; t++) acc[t] = make_float4(0.f, 0.f, 0.f, 0.f);

        for (int ch = 0; ch < WS_; ch++) {
            float sc[WS_];
            float cmax = -1e30f;
            int rowoff = (i1 - ch + WS_ - 1) * (2 * WS_ - 1);
            #pragma unroll
            for (int u = 0; u < WS_; u++) {
                int kj = ch * WS_ + u;
                const float4* kk = (const float4*)&ks[kj * HD_];
                float dsum = 0.f;
                #pragma unroll
                for (int t = 0; t < 8; t++) {
                    float4 kv = kk[t];
                    dsum += q[t].x * kv.x + q[t].y * kv.y + q[t].z * kv.z + q[t].w * kv.w;
                }
                float msk = (lab[kj] != lq) ? -100.f : 0.f;
                sc[u] = dsum * scale + stable[rowoff + (j1 - u + WS_ - 1)] + msk;
                cmax = fmaxf(cmax, sc[u]);
            }
            float nm = fmaxf(m, cmax);
            float corr = __expf(m - nm);
            ssum *= corr;
            #pragma unroll
            for (int t = 0; t < 8; t++) {
                acc[t].x *= corr; acc[t].y *= corr; acc[t].z *= corr; acc[t].w *= corr;
            }
            #pragma unroll
            for (int u = 0; u < WS_; u++) {
                float p = __expf(sc[u] - nm);
                ssum += p;
                const float4* vv = (const float4*)&vs[(ch * WS_ + u) * HD_];
                #pragma unroll
                for (int t = 0; t < 8; t++) {
                    float4 vb = vv[t];
                    acc[t].x += p * vb.x; acc[t].y += p * vb.y;
                    acc[t].z += p * vb.z; acc[t].w += p * vb.w;
                }
            }
            m = nm;
        }
        float inv = 1.f / ssum;
        __half2* og = (__half2*)(ctx + ((size_t)(w * L_ + tid)) * C_ + head * HD_);
        #pragma unroll
        for (int t = 0; t < 8; t++) {
            og[2 * t + 0] = __floats2half2_rn(acc[t].x * inv, acc[t].y * inv);
            og[2 * t + 1] = __floats2half2_rn(acc[t].z * inv, acc[t].w * inv);
        }
    }
}

// ---------------- driver ----------------------------------------------------
extern "C" void kernel_launch(void* const* d_in, const int* in_sizes, int n_in,
                              void* d_out, int out_size)
{
    const float* hidden = (const float*)d_in[0];
    const float* ln1_g  = (const float*)d_in[1];
    const float* ln1_b  = (const float*)d_in[2];
    const float* wq = (const float*)d_in[3];
    const float* bq = (const float*)d_in[4];
    const float* wk = (const float*)d_in[5];
    const float* bk = (const float*)d_in[6];
    const float* wv = (const float*)d_in[7];
    const float* bv = (const float*)d_in[8];
    const float* wo = (const float*)d_in[9];
    const float* bo = (const float*)d_in[10];
    const float* table = (const float*)d_in[11];
    const float* ln2_g = (const float*)d_in[12];
    const float* ln2_b = (const float*)d_in[13];
    const float* w1 = (const float*)d_in[14];
    const float* b1 = (const float*)d_in[15];
    const float* w2 = (const float*)d_in[16];
    const float* b2 = (const float*)d_in[17];
    float* out = (float*)d_out;

    __half *pah, *pch, *pfh, *pwh;
    float *pq, *pk, *pv, *phs;
    cudaGetSymbolAddress((void**)&pah, g_ah);
    cudaGetSymbolAddress((void**)&pq,  g_q);
    cudaGetSymbolAddress((void**)&pk,  g_k);
    cudaGetSymbolAddress((void**)&pv,  g_v);
    cudaGetSymbolAddress((void**)&pch, g_ch);
    cudaGetSymbolAddress((void**)&phs, g_hs);
    cudaGetSymbolAddress((void**)&pfh, g_fh);
    cudaGetSymbolAddress((void**)&pwh, g_wh);

    __half* whq = pwh;
    __half* whk = pwh + 262144;
    __half* whv = pwh + 524288;
    __half* who = pwh + 786432;
    __half* wh1 = pwh + 1048576;
    __half* wh2 = pwh + 2097152;

    const int GSMEM = 3 * STG_W * 4;  // 81408 bytes
    cudaFuncSetAttribute(gemm_h, cudaFuncAttributeMaxDynamicSharedMemorySize, GSMEM);

    // 0) weight conversion -> pair-interleaved half
    convw_kernel<<<(C_ * C_ + 255) / 256, 256>>>(wq, whq, C_, C_);
    convw_kernel<<<(C_ * C_ + 255) / 256, 256>>>(wk, whk, C_, C_);
    convw_kernel<<<(C_ * C_ + 255) / 256, 256>>>(wv, whv, C_, C_);
    convw_kernel<<<(C_ * C_ + 255) / 256, 256>>>(wo, who, C_, C_);
    convw_kernel<<<(C_ * FF_ + 255) / 256, 256>>>(w1, wh1, C_, FF_);
    convw_kernel<<<(FF_ * C_ + 255) / 256, 256>>>(w2, wh2, FF_, C_);

    // 1) LN1 + shift + window partition -> g_ah (half)
    ln_kernel<<<TOK_, 128>>>(hidden, ln1_g, ln1_b, pah);

    // 2) QKV projections -> f32
    dim3 gp(TOK_ / BM, C_ / BN);
    gemm_h<<<gp, 256, GSMEM>>>(pah, whq, bq, nullptr, pq, C_, C_, 0);
    gemm_h<<<gp, 256, GSMEM>>>(pah, whk, bk, nullptr, pk, C_, C_, 0);
    gemm_h<<<gp, 256, GSMEM>>>(pah, whv, bv, nullptr, pv, C_, C_, 0);

    // 3) windowed attention -> g_ch (half)
    attn_kernel<<<dim3(B_ * NW_, NH_), 128>>>(pq, pk, pv, table, pch);

    // 4) output projection -> g_q (f32, reuse)
    gemm_h<<<gp, 256, GSMEM>>>(pch, who, bo, nullptr, pq, C_, C_, 0);

    // 5) reverse + residual + LN2 -> g_hs (f32), g_ah (half, reuse)
    rev_res_ln_kernel<<<TOK_, 128>>>(hidden, pq, ln2_g, ln2_b, phs, pah);

    // 6) FFN1 + GELU -> g_fh (half)
    gemm_h<<<dim3(TOK_ / BM, FF_ / BN), 256, GSMEM>>>(pah, wh1, b1, nullptr, pfh, FF_, C_, 1);

    // 7) FFN2 + residual -> out (f32)
    gemm_h<<<gp, 256, GSMEM>>>(pfh, wh2, b2, phs, out, C_, FF_, 2);
}

// round 10
// speedup vs baseline: 5.4892x; 1.0326x over previous
#include <cuda_runtime.h>
#include <cuda_fp16.h>
#include <math.h>
#include <stdint.h>

// ---------------- static config ----------------
#define B_   8
#define H_   80
#define W_   60
#define C_   512
#define WS_  10
#define SHIFT_ 5
#define NH_  16
#define HD_  32
#define L_   100
#define NWH_ 8
#define NWW_ 6
#define NW_  48
#define TOK_ (B_*H_*W_)    // 38400
#define FF_  2048

// ---------------- scratch ----------------
__device__ __half g_ah[(size_t)TOK_*C_];
__device__ float  g_q [(size_t)TOK_*C_];
__device__ float  g_k [(size_t)TOK_*C_];
__device__ float  g_v [(size_t)TOK_*C_];
__device__ __half g_ch[(size_t)TOK_*C_];
__device__ float  g_hs[(size_t)TOK_*C_];
__device__ __half g_fh[(size_t)TOK_*FF_];
__device__ __half g_wh[3145728];           // qkv(0..786431) o(786432..) w1(1048576..) w2(2097152..)
__device__ float  g_bqkv[3*C_];

// ---------------- helpers ----------------
__device__ __forceinline__ uint32_t smem_u32(const void* p) {
    uint32_t a;
    asm("{ .reg .u64 t; cvta.to.shared.u64 t, %1; cvt.u32.u64 %0, t; }" : "=r"(a) : "l"(p));
    return a;
}
__device__ __forceinline__ void cp16(uint32_t s, const void* g) {
    asm volatile("cp.async.cg.shared.global [%0], [%1], 16;" :: "r"(s), "l"(g) : "memory");
}
__device__ __forceinline__ void mma_f16(float* d, const uint32_t* a, const uint32_t* b) {
    asm volatile(
        "mma.sync.aligned.m16n8k16.row.col.f32.f16.f16.f32 "
        "{%0,%1,%2,%3}, {%4,%5,%6,%7}, {%8,%9}, {%0,%1,%2,%3};"
        : "+f"(d[0]), "+f"(d[1]), "+f"(d[2]), "+f"(d[3])
        : "r"(a[0]), "r"(a[1]), "r"(a[2]), "r"(a[3]), "r"(b[0]), "r"(b[1]));
}
__device__ __forceinline__ void ldsm4(uint32_t* r, uint32_t addr) {
    asm volatile("ldmatrix.sync.aligned.m8n8.x4.shared.b16 {%0,%1,%2,%3}, [%4];"
                 : "=r"(r[0]), "=r"(r[1]), "=r"(r[2]), "=r"(r[3]) : "r"(addr));
}

// ---------------- weight conversion: W[K][N] -> out[k/2][Ntot][2] half ------
__global__ __launch_bounds__(256) void convw_kernel(
    const float* __restrict__ w, __half* __restrict__ out, int K, int N,
    int Ntot, int noff)
{
    int idx = blockIdx.x * 256 + threadIdx.x;
    if (idx >= K * N) return;
    int k = idx / N, n = idx - k * N;
    out[(size_t)(k >> 1) * (2 * Ntot) + 2 * (noff + n) + (k & 1)] = __float2half(w[idx]);
}
__global__ __launch_bounds__(256) void concat_bias_kernel(
    const float* __restrict__ b0, const float* __restrict__ b1,
    const float* __restrict__ b2, float* __restrict__ out)
{
    int i = blockIdx.x * 256 + threadIdx.x;
    if (i >= 3 * C_) return;
    int seg = i >> 9, n = i & 511;
    out[i] = (seg == 0) ? b0[n] : (seg == 1) ? b1[n] : b2[n];
}

// ---------------- block reduction ----------------
__device__ __forceinline__ float block_sum_128(float v) {
    #pragma unroll
    for (int o = 16; o > 0; o >>= 1) v += __shfl_xor_sync(0xffffffffu, v, o);
    __shared__ float sh[4];
    int lane = threadIdx.x & 31, wid = threadIdx.x >> 5;
    __syncthreads();
    if (lane == 0) sh[wid] = v;
    __syncthreads();
    return sh[0] + sh[1] + sh[2] + sh[3];
}

// ---------------- LN1 + shift + window partition -> half --------------------
__global__ __launch_bounds__(128) void ln_kernel(
    const float* __restrict__ x, const float* __restrict__ g,
    const float* __restrict__ bt, __half* __restrict__ out)
{
    int r = blockIdx.x;
    int wg = r / L_, l = r % L_;
    int b = wg / NW_, wi = wg % NW_;
    int wh = wi / NWW_, ww = wi % NWW_;
    int h = (wh * WS_ + l / WS_ + SHIFT_) % H_;
    int w = (ww * WS_ + l % WS_ + SHIFT_) % W_;
    size_t in_row = (size_t)b * (H_ * W_) + h * W_ + w;

    const float* row = x + in_row * C_;
    float v[4]; float s = 0.f;
    #pragma unroll
    for (int e = 0; e < 4; e++) { v[e] = row[threadIdx.x + e * 128]; s += v[e]; }
    float mean = block_sum_128(s) * (1.f / C_);
    float d2 = 0.f;
    #pragma unroll
    for (int e = 0; e < 4; e++) { float d = v[e] - mean; d2 += d * d; }
    float var = block_sum_128(d2) * (1.f / C_);
    float rstd = rsqrtf(var + 1e-5f);
    __half* o = out + (size_t)r * C_;
    #pragma unroll
    for (int e = 0; e < 4; e++) {
        int c = threadIdx.x + e * 128;
        o[c] = __float2half((v[e] - mean) * rstd * g[c] + bt[c]);
    }
}

// ---- window-reverse + un-shift + residual + LN2 ----------------------------
__global__ __launch_bounds__(128) void rev_res_ln_kernel(
    const float* __restrict__ hidden, const float* __restrict__ att,
    const float* __restrict__ g, const float* __restrict__ bt,
    float* __restrict__ hs, __half* __restrict__ lnout)
{
    int t = blockIdx.x;
    int b = t / (H_ * W_), p = t % (H_ * W_);
    int h = p / W_, w = p % W_;
    int hp = (h + H_ - SHIFT_) % H_;
    int wp = (w + W_ - SHIFT_) % W_;
    int src = (b * NW_ + (hp / WS_) * NWW_ + wp / WS_) * L_ + (hp % WS_) * WS_ + (wp % WS_);

    const float* hr = hidden + (size_t)t * C_;
    const float* ar = att + (size_t)src * C_;
    float* hsr = hs + (size_t)t * C_;
    __half* lor = lnout + (size_t)t * C_;

    float v[4]; float s = 0.f;
    #pragma unroll
    for (int e = 0; e < 4; e++) {
        int c = threadIdx.x + e * 128;
        v[e] = hr[c] + ar[c];
        hsr[c] = v[e];
        s += v[e];
    }
    float mean = block_sum_128(s) * (1.f / C_);
    float d2 = 0.f;
    #pragma unroll
    for (int e = 0; e < 4; e++) { float d = v[e] - mean; d2 += d * d; }
    float var = block_sum_128(d2) * (1.f / C_);
    float rstd = rsqrtf(var + 1e-5f);
    #pragma unroll
    for (int e = 0; e < 4; e++) {
        int c = threadIdx.x + e * 128;
        lor[c] = __float2half((v[e] - mean) * rstd * g[c] + bt[c]);
    }
}

// ---------------- fp16 mma.sync GEMM (ldmatrix A, 3-stage) ------------------
// epi: 0 f32 out; 1 half out + GELU; 2 f32 out + res; 3 qkv split (out,out2,out3)
#define BM 128
#define BN 128
#define BK 32
#define ASW 36
#define BSW 136
#define STG_W (BM * ASW + 16 * BSW)

__global__ __launch_bounds__(256, 2) void gemm_h(
    const __half* __restrict__ Ah, const __half* __restrict__ Wh,
    const float* __restrict__ bias, const float* __restrict__ res,
    void* __restrict__ outp, int Nout, int K, int epi,
    float* __restrict__ out2, float* __restrict__ out3)
{
    extern __shared__ uint32_t sm[];

    int tid = threadIdx.x, lane = tid & 31, wid = tid >> 5;
    int tok0 = blockIdx.x * BM, n0 = blockIdx.y * BN;
    int wm0 = (wid & 1) * 64, wn0 = (wid >> 1) * 32;

    int a_row = tid >> 2, a_seg = tid & 3;
    int b_row = tid >> 4, b_seg = tid & 15;
    const __half* a_gp = Ah + (size_t)(tok0 + a_row) * K + a_seg * 8;
    const __half* b_gp = Wh + (size_t)b_row * (2 * Nout) + n0 * 2 + b_seg * 8;

    float acc[4][4][4];
    #pragma unroll
    for (int mt = 0; mt < 4; mt++)
        #pragma unroll
        for (int nt = 0; nt < 4; nt++)
            #pragma unroll
            for (int e = 0; e < 4; e++) acc[mt][nt][e] = 0.f;

    const int nch = K / BK;

    auto issue = [&](int c) {
        int s = c % 3;
        uint32_t* Ab = sm + s * STG_W;
        uint32_t* Bb = Ab + BM * ASW;
        int k0 = c * BK;
        #pragma unroll
        for (int i = 0; i < 2; i++)
            cp16(smem_u32(Ab + (a_row + i * 64) * ASW + a_seg * 4),
                 a_gp + (size_t)(i * 64) * K + k0);
        #pragma unroll
        for (int i = 0; i < 2; i++)
            cp16(smem_u32(Bb + b_row * BSW + (b_seg + i * 16) * 4),
                 b_gp + (size_t)(k0 >> 1) * (2 * Nout) + i * 128);
        asm volatile("cp.async.commit_group;" ::: "memory");
    };

    issue(0);
    issue(1);

    // per-lane ldmatrix base: row = (lane&15), khalf = (lane>>4)*4 words
    int lrow = lane & 15, lkh = (lane >> 4) * 4;

    for (int c = 0; c < nch; c++) {
        if (c < nch - 1) {
            asm volatile("cp.async.wait_group 1;" ::: "memory");
        } else {
            asm volatile("cp.async.wait_group 0;" ::: "memory");
        }
        __syncthreads();
        if (c + 2 < nch) issue(c + 2);

        int s = c % 3;
        const uint32_t* A = sm + s * STG_W;
        const uint32_t* Bm = A + BM * ASW;
        int c4 = lane & 3, bn = lane >> 2;
        #pragma unroll
        for (int ks = 0; ks < 2; ks++) {
            uint32_t a[4][4], b[4][2];
            #pragma unroll
            for (int mt = 0; mt < 4; mt++) {
                uint32_t addr = smem_u32(A + (wm0 + mt * 16 + lrow) * ASW + ks * 8 + lkh);
                ldsm4(a[mt], addr);
            }
            int pb0 = (ks * 8 + c4) * BSW;
            int pb1 = (ks * 8 + c4 + 4) * BSW;
            #pragma unroll
            for (int nt = 0; nt < 4; nt++) {
                int n = wn0 + nt * 8 + bn;
                b[nt][0] = Bm[pb0 + n];
                b[nt][1] = Bm[pb1 + n];
            }
            #pragma unroll
            for (int mt = 0; mt < 4; mt++)
                #pragma unroll
                for (int nt = 0; nt < 4; nt++)
                    mma_f16(acc[mt][nt], a[mt], b[nt]);
        }
    }

    // ---- epilogue ----
    float* fout = (float*)outp;
    int ostride = Nout, ncol0 = n0;
    if (epi == 3) {
        int seg = n0 >> 9;
        fout = (seg == 0) ? (float*)outp : (seg == 1) ? out2 : out3;
        ostride = C_;
        ncol0 = n0 & 511;
    }
    #pragma unroll
    for (int mt = 0; mt < 4; mt++) {
        #pragma unroll
        for (int nt = 0; nt < 4; nt++) {
            int r0 = tok0 + wm0 + mt * 16 + (lane >> 2);
            int cg = n0 + wn0 + nt * 8 + 2 * (lane & 3);       // for bias
            int c0 = ncol0 + wn0 + nt * 8 + 2 * (lane & 3);    // for output
            float2 bv = *(const float2*)(bias + cg);
            #pragma unroll
            for (int h = 0; h < 2; h++) {
                int row = r0 + h * 8;
                float v0 = acc[mt][nt][2 * h + 0] + bv.x;
                float v1 = acc[mt][nt][2 * h + 1] + bv.y;
                if (epi == 1) {
                    v0 = 0.5f * v0 * (1.f + erff(v0 * 0.70710678118654752f));
                    v1 = 0.5f * v1 * (1.f + erff(v1 * 0.70710678118654752f));
                    *(__half2*)((__half*)outp + (size_t)row * Nout + c0) =
                        __floats2half2_rn(v0, v1);
                } else {
                    if (epi == 2) {
                        float2 rr = *(const float2*)(res + (size_t)row * Nout + c0);
                        v0 += rr.x; v1 += rr.y;
                    }
                    float2 o; o.x = v0; o.y = v1;
                    *(float2*)(fout + (size_t)row * ostride + c0) = o;
                }
            }
        }
    }
}

// ---------------- windowed attention (f32 in, half ctx out) -----------------
__global__ __launch_bounds__(128) void attn_kernel(
    const float* __restrict__ Q, const float* __restrict__ K,
    const float* __restrict__ V, const float* __restrict__ table,
    __half* __restrict__ ctx)
{
    int w = blockIdx.x;
    int head = blockIdx.y;
    int wi = w % NW_;
    int wh = wi / NWW_, ww = wi % NWW_;

    __shared__ float ks[L_ * HD_];
    __shared__ float vs[L_ * HD_];
    __shared__ float stable[(2 * WS_ - 1) * (2 * WS_ - 1)];
    __shared__ int   lab[L_];

    int tid = threadIdx.x;
    for (int idx = tid; idx < L_ * HD_; idx += 128) {
        int l = idx >> 5, d = idx & 31;
        size_t gi = ((size_t)(w * L_ + l)) * C_ + head * HD_ + d;
        ks[idx] = K[gi];
        vs[idx] = V[gi];
    }
    for (int idx = tid; idx < 361; idx += 128) stable[idx] = table[idx * NH_ + head];
    if (tid < L_) {
        int i = tid / WS_, j = tid % WS_;
        int h = wh * WS_ + i, x = ww * WS_ + j;
        int rh = (h < H_ - WS_) ? 0 : ((h < H_ - SHIFT_) ? 1 : 2);
        int rw = (x < W_ - WS_) ? 0 : ((x < W_ - SHIFT_) ? 1 : 2);
        lab[tid] = rh * 3 + rw;
    }
    __syncthreads();

    if (tid < L_) {
        const float scale = 0.17677669529663687f;
        int i1 = tid / WS_, j1 = tid % WS_;
        int lq = lab[tid];
        float4 q[8];
        const float4* qg = (const float4*)(Q + ((size_t)(w * L_ + tid)) * C_ + head * HD_);
        #pragma unroll
        for (int t = 0; t < 8; t++) q[t] = qg[t];

        float m = -1e30f, ssum = 0.f;
        float4 acc[8];
        #pragma unroll
        for (int t = 0; t < 8; t++) acc[t] = make_float4(0.f, 0.f, 0.f, 0.f);

        for (int ch = 0; ch < WS_; ch++) {
            float sc[WS_];
            float cmax = -1e30f;
            int rowoff = (i1 - ch + WS_ - 1) * (2 * WS_ - 1);
            #pragma unroll
            for (int u = 0; u < WS_; u++) {
                int kj = ch * WS_ + u;
                const float4* kk = (const float4*)&ks[kj * HD_];
                float dsum = 0.f;
                #pragma unroll
                for (int t = 0; t < 8; t++) {
                    float4 kv = kk[t];
                    dsum += q[t].x * kv.x + q[t].y * kv.y + q[t].z * kv.z + q[t].w * kv.w;
                }
                float msk = (lab[kj] != lq) ? -100.f : 0.f;
                sc[u] = dsum * scale + stable[rowoff + (j1 - u + WS_ - 1)] + msk;
                cmax = fmaxf(cmax, sc[u]);
            }
            float nm = fmaxf(m, cmax);
            float corr = __expf(m - nm);
            ssum *= corr;
            #pragma unroll
            for (int t = 0; t < 8; t++) {
                acc[t].x *= corr; acc[t].y *= corr; acc[t].z *= corr; acc[t].w *= corr;
            }
            #pragma unroll
            for (int u = 0; u < WS_; u++) {
                float p = __expf(sc[u] - nm);
                ssum += p;
                const float4* vv = (const float4*)&vs[(ch * WS_ + u) * HD_];
                #pragma unroll
                for (int t = 0; t < 8; t++) {
                    float4 vb = vv[t];
                    acc[t].x += p * vb.x; acc[t].y += p * vb.y;
                    acc[t].z += p * vb.z; acc[t].w += p * vb.w;
                }
            }
            m = nm;
        }
        float inv = 1.f / ssum;
        __half2* og = (__half2*)(ctx + ((size_t)(w * L_ + tid)) * C_ + head * HD_);
        #pragma unroll
        for (int t = 0; t < 8; t++) {
            og[2 * t + 0] = __floats2half2_rn(acc[t].x * inv, acc[t].y * inv);
            og[2 * t + 1] = __floats2half2_rn(acc[t].z * inv, acc[t].w * inv);
        }
    }
}

// ---------------- driver ----------------------------------------------------
extern "C" void kernel_launch(void* const* d_in, const int* in_sizes, int n_in,
                              void* d_out, int out_size)
{
    const float* hidden = (const float*)d_in[0];
    const float* ln1_g  = (const float*)d_in[1];
    const float* ln1_b  = (const float*)d_in[2];
    const float* wq = (const float*)d_in[3];
    const float* bq = (const float*)d_in[4];
    const float* wk = (const float*)d_in[5];
    const float* bk = (const float*)d_in[6];
    const float* wv = (const float*)d_in[7];
    const float* bv = (const float*)d_in[8];
    const float* wo = (const float*)d_in[9];
    const float* bo = (const float*)d_in[10];
    const float* table = (const float*)d_in[11];
    const float* ln2_g = (const float*)d_in[12];
    const float* ln2_b = (const float*)d_in[13];
    const float* w1 = (const float*)d_in[14];
    const float* b1 = (const float*)d_in[15];
    const float* w2 = (const float*)d_in[16];
    const float* b2 = (const float*)d_in[17];
    float* out = (float*)d_out;

    __half *pah, *pch, *pfh, *pwh;
    float *pq, *pk, *pv, *phs, *pbqkv;
    cudaGetSymbolAddress((void**)&pah, g_ah);
    cudaGetSymbolAddress((void**)&pq,  g_q);
    cudaGetSymbolAddress((void**)&pk,  g_k);
    cudaGetSymbolAddress((void**)&pv,  g_v);
    cudaGetSymbolAddress((void**)&pch, g_ch);
    cudaGetSymbolAddress((void**)&phs, g_hs);
    cudaGetSymbolAddress((void**)&pfh, g_fh);
    cudaGetSymbolAddress((void**)&pwh, g_wh);
    cudaGetSymbolAddress((void**)&pbqkv, g_bqkv);

    __half* whqkv = pwh;                 // [256][3072] half = 786432
    __half* who = pwh + 786432;
    __half* wh1 = pwh + 1048576;
    __half* wh2 = pwh + 2097152;

    const int GSMEM = 3 * STG_W * 4;
    cudaFuncSetAttribute(gemm_h, cudaFuncAttributeMaxDynamicSharedMemorySize, GSMEM);

    // 0) weight/bias conversion
    convw_kernel<<<(C_ * C_ + 255) / 256, 256>>>(wq, whqkv, C_, C_, 3 * C_, 0);
    convw_kernel<<<(C_ * C_ + 255) / 256, 256>>>(wk, whqkv, C_, C_, 3 * C_, C_);
    convw_kernel<<<(C_ * C_ + 255) / 256, 256>>>(wv, whqkv, C_, C_, 3 * C_, 2 * C_);
    convw_kernel<<<(C_ * C_ + 255) / 256, 256>>>(wo, who, C_, C_, C_, 0);
    convw_kernel<<<(C_ * FF_ + 255) / 256, 256>>>(w1, wh1, C_, FF_, FF_, 0);
    convw_kernel<<<(FF_ * C_ + 255) / 256, 256>>>(w2, wh2, FF_, C_, C_, 0);
    concat_bias_kernel<<<6, 256>>>(bq, bk, bv, pbqkv);

    // 1) LN1 + shift + window partition -> g_ah
    ln_kernel<<<TOK_, 128>>>(hidden, ln1_g, ln1_b, pah);

    // 2) fused QKV projection -> g_q, g_k, g_v
    gemm_h<<<dim3(TOK_ / BM, (3 * C_) / BN), 256, GSMEM>>>(
        pah, whqkv, pbqkv, nullptr, pq, 3 * C_, C_, 3, pk, pv);

    // 3) windowed attention -> g_ch
    attn_kernel<<<dim3(B_ * NW_, NH_), 128>>>(pq, pk, pv, table, pch);

    // 4) output projection -> g_q
    dim3 gp(TOK_ / BM, C_ / BN);
    gemm_h<<<gp, 256, GSMEM>>>(pch, who, bo, nullptr, pq, C_, C_, 0, nullptr, nullptr);

    // 5) reverse + residual + LN2 -> g_hs, g_ah
    rev_res_ln_kernel<<<TOK_, 128>>>(hidden, pq, ln2_g, ln2_b, phs, pah);

    // 6) FFN1 + GELU -> g_fh
    gemm_h<<<dim3(TOK_ / BM, FF_ / BN), 256, GSMEM>>>(
        pah, wh1, b1, nullptr, pfh, FF_, C_, 1, nullptr, nullptr);

    // 7) FFN2 + residual -> out
    gemm_h<<<gp, 256, GSMEM>>>(pfh, wh2, b2, phs, out, C_, FF_, 2, nullptr, nullptr);
}

// round 13
// speedup vs baseline: 6.8379x; 1.2457x over previous
#include <cuda_runtime.h>
#include <cuda_fp16.h>
#include <math.h>
#include <stdint.h>

// ---------------- static config ----------------
#define B_   8
#define H_   80
#define W_   60
#define C_   512
#define WS_  10
#define SHIFT_ 5
#define NH_  16
#define HD_  32
#define L_   100
#define NWH_ 8
#define NWW_ 6
#define NW_  48
#define TOK_ (B_*H_*W_)    // 38400
#define FF_  2048

// ---------------- scratch ----------------
__device__ __half g_ah[(size_t)TOK_*C_];
__device__ __half g_qh[(size_t)TOK_*C_];
__device__ __half g_kh[(size_t)TOK_*C_];
__device__ __half g_vh[(size_t)TOK_*C_];
__device__ float  g_o [(size_t)TOK_*C_];     // out-proj f32
__device__ __half g_ch[(size_t)TOK_*C_];     // attention ctx half
__device__ float  g_hs[(size_t)TOK_*C_];
__device__ __half g_fh[(size_t)TOK_*FF_];
__device__ __half g_wh[3145728];
__device__ float  g_bqkv[3*C_];

// ---------------- helpers ----------------
__device__ __forceinline__ uint32_t smem_u32(const void* p) {
    uint32_t a;
    asm("{ .reg .u64 t; cvta.to.shared.u64 t, %1; cvt.u32.u64 %0, t; }" : "=r"(a) : "l"(p));
    return a;
}
__device__ __forceinline__ void cp16(uint32_t s, const void* g) {
    asm volatile("cp.async.cg.shared.global [%0], [%1], 16;" :: "r"(s), "l"(g) : "memory");
}
__device__ __forceinline__ void mma_f16(float* d, const uint32_t* a, const uint32_t* b) {
    asm volatile(
        "mma.sync.aligned.m16n8k16.row.col.f32.f16.f16.f32 "
        "{%0,%1,%2,%3}, {%4,%5,%6,%7}, {%8,%9}, {%0,%1,%2,%3};"
        : "+f"(d[0]), "+f"(d[1]), "+f"(d[2]), "+f"(d[3])
        : "r"(a[0]), "r"(a[1]), "r"(a[2]), "r"(a[3]), "r"(b[0]), "r"(b[1]));
}
__device__ __forceinline__ void ldsm4(uint32_t* r, uint32_t addr) {
    asm volatile("ldmatrix.sync.aligned.m8n8.x4.shared.b16 {%0,%1,%2,%3}, [%4];"
                 : "=r"(r[0]), "=r"(r[1]), "=r"(r[2]), "=r"(r[3]) : "r"(addr));
}
__device__ __forceinline__ uint32_t pack_h2(float a, float b) {
    __half2 h = __floats2half2_rn(a, b);
    return *(uint32_t*)&h;
}

// ---------------- weight conversion ----------------
__global__ __launch_bounds__(256) void convw_kernel(
    const float* __restrict__ w, __half* __restrict__ out, int K, int N,
    int Ntot, int noff)
{
    int idx = blockIdx.x * 256 + threadIdx.x;
    if (idx >= K * N) return;
    int k = idx / N, n = idx - k * N;
    out[(size_t)(k >> 1) * (2 * Ntot) + 2 * (noff + n) + (k & 1)] = __float2half(w[idx]);
}
__global__ __launch_bounds__(256) void concat_bias_kernel(
    const float* __restrict__ b0, const float* __restrict__ b1,
    const float* __restrict__ b2, float* __restrict__ out)
{
    int i = blockIdx.x * 256 + threadIdx.x;
    if (i >= 3 * C_) return;
    int seg = i >> 9, n = i & 511;
    out[i] = (seg == 0) ? b0[n] : (seg == 1) ? b1[n] : b2[n];
}

// ---------------- block reduction ----------------
__device__ __forceinline__ float block_sum_128(float v) {
    #pragma unroll
    for (int o = 16; o > 0; o >>= 1) v += __shfl_xor_sync(0xffffffffu, v, o);
    __shared__ float sh[4];
    int lane = threadIdx.x & 31, wid = threadIdx.x >> 5;
    __syncthreads();
    if (lane == 0) sh[wid] = v;
    __syncthreads();
    return sh[0] + sh[1] + sh[2] + sh[3];
}

// ---------------- LN1 + shift + window partition -> half --------------------
__global__ __launch_bounds__(128) void ln_kernel(
    const float* __restrict__ x, const float* __restrict__ g,
    const float* __restrict__ bt, __half* __restrict__ out)
{
    int r = blockIdx.x;
    int wg = r / L_, l = r % L_;
    int b = wg / NW_, wi = wg % NW_;
    int wh = wi / NWW_, ww = wi % NWW_;
    int h = (wh * WS_ + l / WS_ + SHIFT_) % H_;
    int w = (ww * WS_ + l % WS_ + SHIFT_) % W_;
    size_t in_row = (size_t)b * (H_ * W_) + h * W_ + w;

    const float* row = x + in_row * C_;
    float v[4]; float s = 0.f;
    #pragma unroll
    for (int e = 0; e < 4; e++) { v[e] = row[threadIdx.x + e * 128]; s += v[e]; }
    float mean = block_sum_128(s) * (1.f / C_);
    float d2 = 0.f;
    #pragma unroll
    for (int e = 0; e < 4; e++) { float d = v[e] - mean; d2 += d * d; }
    float var = block_sum_128(d2) * (1.f / C_);
    float rstd = rsqrtf(var + 1e-5f);
    __half* o = out + (size_t)r * C_;
    #pragma unroll
    for (int e = 0; e < 4; e++) {
        int c = threadIdx.x + e * 128;
        o[c] = __float2half((v[e] - mean) * rstd * g[c] + bt[c]);
    }
}

// ---- window-reverse + un-shift + residual + LN2 ----------------------------
__global__ __launch_bounds__(128) void rev_res_ln_kernel(
    const float* __restrict__ hidden, const float* __restrict__ att,
    const float* __restrict__ g, const float* __restrict__ bt,
    float* __restrict__ hs, __half* __restrict__ lnout)
{
    int t = blockIdx.x;
    int b = t / (H_ * W_), p = t % (H_ * W_);
    int h = p / W_, w = p % W_;
    int hp = (h + H_ - SHIFT_) % H_;
    int wp = (w + W_ - SHIFT_) % W_;
    int src = (b * NW_ + (hp / WS_) * NWW_ + wp / WS_) * L_ + (hp % WS_) * WS_ + (wp % WS_);

    const float* hr = hidden + (size_t)t * C_;
    const float* ar = att + (size_t)src * C_;
    float* hsr = hs + (size_t)t * C_;
    __half* lor = lnout + (size_t)t * C_;

    float v[4]; float s = 0.f;
    #pragma unroll
    for (int e = 0; e < 4; e++) {
        int c = threadIdx.x + e * 128;
        v[e] = hr[c] + ar[c];
        hsr[c] = v[e];
        s += v[e];
    }
    float mean = block_sum_128(s) * (1.f / C_);
    float d2 = 0.f;
    #pragma unroll
    for (int e = 0; e < 4; e++) { float d = v[e] - mean; d2 += d * d; }
    float var = block_sum_128(d2) * (1.f / C_);
    float rstd = rsqrtf(var + 1e-5f);
    #pragma unroll
    for (int e = 0; e < 4; e++) {
        int c = threadIdx.x + e * 128;
        lor[c] = __float2half((v[e] - mean) * rstd * g[c] + bt[c]);
    }
}

// ---------------- fp16 mma.sync GEMM (ldmatrix A, 3-stage) ------------------
// epi: 0 f32; 1 half+GELU; 2 f32+res; 3 half qkv split
#define BM 128
#define BN 128
#define BK 32
#define ASW 36
#define BSW 136
#define STG_W (BM * ASW + 16 * BSW)

__global__ __launch_bounds__(256, 2) void gemm_h(
    const __half* __restrict__ Ah, const __half* __restrict__ Wh,
    const float* __restrict__ bias, const float* __restrict__ res,
    void* __restrict__ outp, int Nout, int K, int epi,
    void* __restrict__ out2, void* __restrict__ out3)
{
    extern __shared__ uint32_t sm[];

    int tid = threadIdx.x, lane = tid & 31, wid = tid >> 5;
    int tok0 = blockIdx.x * BM, n0 = blockIdx.y * BN;
    int wm0 = (wid & 1) * 64, wn0 = (wid >> 1) * 32;

    int a_row = tid >> 2, a_seg = tid & 3;
    int b_row = tid >> 4, b_seg = tid & 15;
    const __half* a_gp = Ah + (size_t)(tok0 + a_row) * K + a_seg * 8;
    const __half* b_gp = Wh + (size_t)b_row * (2 * Nout) + n0 * 2 + b_seg * 8;

    float acc[4][4][4];
    #pragma unroll
    for (int mt = 0; mt < 4; mt++)
        #pragma unroll
        for (int nt = 0; nt < 4; nt++)
            #pragma unroll
            for (int e = 0; e < 4; e++) acc[mt][nt][e] = 0.f;

    const int nch = K / BK;

    auto issue = [&](int c) {
        int s = c % 3;
        uint32_t* Ab = sm + s * STG_W;
        uint32_t* Bb = Ab + BM * ASW;
        int k0 = c * BK;
        #pragma unroll
        for (int i = 0; i < 2; i++)
            cp16(smem_u32(Ab + (a_row + i * 64) * ASW + a_seg * 4),
                 a_gp + (size_t)(i * 64) * K + k0);
        #pragma unroll
        for (int i = 0; i < 2; i++)
            cp16(smem_u32(Bb + b_row * BSW + (b_seg + i * 16) * 4),
                 b_gp + (size_t)(k0 >> 1) * (2 * Nout) + i * 128);
        asm volatile("cp.async.commit_group;" ::: "memory");
    };

    issue(0);
    issue(1);

    int lrow = lane & 15, lkh = (lane >> 4) * 4;

    for (int c = 0; c < nch; c++) {
        if (c < nch - 1) {
            asm volatile("cp.async.wait_group 1;" ::: "memory");
        } else {
            asm volatile("cp.async.wait_group 0;" ::: "memory");
        }
        __syncthreads();
        if (c + 2 < nch) issue(c + 2);

        int s = c % 3;
        const uint32_t* A = sm + s * STG_W;
        const uint32_t* Bm = A + BM * ASW;
        int c4 = lane & 3, bn = lane >> 2;
        #pragma unroll
        for (int ks = 0; ks < 2; ks++) {
            uint32_t a[4][4], b[4][2];
            #pragma unroll
            for (int mt = 0; mt < 4; mt++) {
                uint32_t addr = smem_u32(A + (wm0 + mt * 16 + lrow) * ASW + ks * 8 + lkh);
                ldsm4(a[mt], addr);
            }
            int pb0 = (ks * 8 + c4) * BSW;
            int pb1 = (ks * 8 + c4 + 4) * BSW;
            #pragma unroll
            for (int nt = 0; nt < 4; nt++) {
                int n = wn0 + nt * 8 + bn;
                b[nt][0] = Bm[pb0 + n];
                b[nt][1] = Bm[pb1 + n];
            }
            #pragma unroll
            for (int mt = 0; mt < 4; mt++)
                #pragma unroll
                for (int nt = 0; nt < 4; nt++)
                    mma_f16(acc[mt][nt], a[mt], b[nt]);
        }
    }

    // ---- epilogue ----
    __half* hsplit = nullptr;
    int ncol0 = n0;
    if (epi == 3) {
        int seg = n0 >> 9;
        hsplit = (seg == 0) ? (__half*)outp : (seg == 1) ? (__half*)out2 : (__half*)out3;
        ncol0 = n0 & 511;
    }
    #pragma unroll
    for (int mt = 0; mt < 4; mt++) {
        #pragma unroll
        for (int nt = 0; nt < 4; nt++) {
            int r0 = tok0 + wm0 + mt * 16 + (lane >> 2);
            int cg = n0 + wn0 + nt * 8 + 2 * (lane & 3);
            int c0 = ncol0 + wn0 + nt * 8 + 2 * (lane & 3);
            float2 bv = *(const float2*)(bias + cg);
            #pragma unroll
            for (int h = 0; h < 2; h++) {
                int row = r0 + h * 8;
                float v0 = acc[mt][nt][2 * h + 0] + bv.x;
                float v1 = acc[mt][nt][2 * h + 1] + bv.y;
                if (epi == 3) {
                    *(__half2*)(hsplit + (size_t)row * C_ + c0) = __floats2half2_rn(v0, v1);
                } else if (epi == 1) {
                    v0 = 0.5f * v0 * (1.f + erff(v0 * 0.70710678118654752f));
                    v1 = 0.5f * v1 * (1.f + erff(v1 * 0.70710678118654752f));
                    *(__half2*)((__half*)outp + (size_t)row * Nout + c0) =
                        __floats2half2_rn(v0, v1);
                } else {
                    if (epi == 2) {
                        float2 rr = *(const float2*)(res + (size_t)row * Nout + c0);
                        v0 += rr.x; v1 += rr.y;
                    }
                    float2 o; o.x = v0; o.y = v1;
                    *(float2*)((float*)outp + (size_t)row * Nout + c0) = o;
                }
            }
        }
    }
}

// ---------------- tensor-core windowed attention ----------------------------
// block = (window, head), 4 warps. S=QK^T (128x112, K=32), softmax, P@V.
__global__ __launch_bounds__(128) void attn_mma(
    const __half* __restrict__ Qh, const __half* __restrict__ Kh,
    const __half* __restrict__ Vh, const float* __restrict__ table,
    __half* __restrict__ ctx)
{
    int w = blockIdx.x, head = blockIdx.y;
    int wi = w % NW_;
    int whh = wi / NWW_, www = wi % NWW_;

    __shared__ __half Qs[128][40];
    __shared__ __half Ks[112][40];
    __shared__ __half Vt[32][120];        // Vt2[n][p] word = (V[2p][n], V[2p+1][n])
    __shared__ float stable[361];
    __shared__ int lab[100];

    int tid = threadIdx.x, lane = tid & 31, wid = tid >> 5;

    // zero pads
    for (int i = tid; i < 560; i += 128) {          // Qs rows 100..127
        ((uint32_t*)Qs)[100 * 20 + i] = 0u;
    }
    for (int i = tid; i < 240; i += 128) {          // Ks rows 100..111
        ((uint32_t*)Ks)[100 * 20 + i] = 0u;
    }
    for (int i = tid; i < 320; i += 128) {          // Vt keys 100..119
        int n = i / 10, c = i % 10;
        ((uint32_t*)Vt)[n * 60 + 50 + c] = 0u;
    }
    // load Q, K
    for (int idx = tid; idx < 400; idx += 128) {
        int l = idx >> 2, ch = idx & 3;
        size_t gi = (size_t)(w * L_ + l) * C_ + head * HD_ + ch * 8;
        *(int4*)&Qs[l][ch * 8] = *(const int4*)(Qh + gi);
        *(int4*)&Ks[l][ch * 8] = *(const int4*)(Kh + gi);
    }
    // load V transposed (key pairs)
    for (int idx = tid; idx < 800; idx += 128) {
        int p = idx >> 4, j = idx & 15;
        const __half2 a = *(const __half2*)(Vh + (size_t)(w * L_ + 2 * p) * C_ + head * HD_ + 2 * j);
        const __half2 b = *(const __half2*)(Vh + (size_t)(w * L_ + 2 * p + 1) * C_ + head * HD_ + 2 * j);
        *(__half2*)&Vt[2 * j][2 * p]     = __halves2half2(__low2half(a),  __low2half(b));
        *(__half2*)&Vt[2 * j + 1][2 * p] = __halves2half2(__high2half(a), __high2half(b));
    }
    for (int i = tid; i < 361; i += 128) stable[i] = table[i * NH_ + head];
    if (tid < 100) {
        int i = tid / WS_, j = tid % WS_;
        int h = whh * WS_ + i, x = www * WS_ + j;
        int rh = (h < H_ - WS_) ? 0 : ((h < H_ - SHIFT_) ? 1 : 2);
        int rw = (x < W_ - WS_) ? 0 : ((x < W_ - SHIFT_) ? 1 : 2);
        lab[tid] = rh * 3 + rw;
    }
    __syncthreads();

    const float scale = 0.17677669529663687f;
    int wm0 = wid * 32;
    int c4 = lane & 3, bn = lane >> 2;
    float ctxa[2][4][4];
    #pragma unroll
    for (int mt = 0; mt < 2; mt++)
        #pragma unroll
        for (int nt = 0; nt < 4; nt++)
            #pragma unroll
            for (int e = 0; e < 4; e++) ctxa[mt][nt][e] = 0.f;
    float inva[2][2];

    const uint32_t* Ks2 = (const uint32_t*)Ks;   // stride 20 words
    const uint32_t* Vt2 = (const uint32_t*)Vt;   // stride 60 words

    #pragma unroll
    for (int mt = 0; mt < 2; mt++) {
        float sacc[14][4];
        #pragma unroll
        for (int nt = 0; nt < 14; nt++)
            #pragma unroll
            for (int e = 0; e < 4; e++) sacc[nt][e] = 0.f;

        // ---- S = Q K^T ----
        uint32_t afr[2][4];
        #pragma unroll
        for (int kk = 0; kk < 2; kk++) {
            uint32_t addr = smem_u32(&Qs[wm0 + mt * 16 + (lane & 15)][kk * 16 + (lane >> 4) * 8]);
            ldsm4(afr[kk], addr);
        }
        #pragma unroll
        for (int nt = 0; nt < 14; nt++) {
            int key = nt * 8 + bn;
            #pragma unroll
            for (int kk = 0; kk < 2; kk++) {
                uint32_t b[2];
                b[0] = Ks2[key * 20 + kk * 8 + c4];
                b[1] = Ks2[key * 20 + kk * 8 + c4 + 4];
                mma_f16(sacc[nt], afr[kk], b);
            }
        }

        // ---- scale + bias + mask, row softmax ----
        int r0 = wm0 + mt * 16 + bn, r1 = r0 + 8;
        int r0c = (r0 < 100) ? r0 : 99;
        int r1c = (r1 < 100) ? r1 : 99;
        int i1a = r0c / 10, j1a = r0c - i1a * 10, la = lab[r0c];
        int i1b = r1c / 10, j1b = r1c - i1b * 10, lb = lab[r1c];

        float mx0 = -1e30f, mx1 = -1e30f;
        #pragma unroll
        for (int nt = 0; nt < 14; nt++) {
            int c0 = nt * 8 + 2 * c4;
            if (c0 >= 100) {
                sacc[nt][0] = sacc[nt][1] = sacc[nt][2] = sacc[nt][3] = -1e30f;
            } else {
                int i2a = c0 / 10, j2a = c0 - i2a * 10;
                int cc1 = c0 + 1;
                int i2b = cc1 / 10, j2b = cc1 - i2b * 10;
                int lc0 = lab[c0], lc1 = lab[cc1];
                float m00 = (lc0 != la) ? -100.f : 0.f;
                float m01 = (lc1 != la) ? -100.f : 0.f;
                float m10 = (lc0 != lb) ? -100.f : 0.f;
                float m11 = (lc1 != lb) ? -100.f : 0.f;
                float s0 = sacc[nt][0] * scale + stable[(i1a - i2a + 9) * 19 + (j1a - j2a + 9)] + m00;
                float s1 = sacc[nt][1] * scale + stable[(i1a - i2b + 9) * 19 + (j1a - j2b + 9)] + m01;
                float s2 = sacc[nt][2] * scale + stable[(i1b - i2a + 9) * 19 + (j1b - j2a + 9)] + m10;
                float s3 = sacc[nt][3] * scale + stable[(i1b - i2b + 9) * 19 + (j1b - j2b + 9)] + m11;
                sacc[nt][0] = s0; sacc[nt][1] = s1; sacc[nt][2] = s2; sacc[nt][3] = s3;
                mx0 = fmaxf(mx0, fmaxf(s0, s1));
                mx1 = fmaxf(mx1, fmaxf(s2, s3));
            }
        }
        mx0 = fmaxf(mx0, __shfl_xor_sync(0xffffffffu, mx0, 1));
        mx0 = fmaxf(mx0, __shfl_xor_sync(0xffffffffu, mx0, 2));
        mx1 = fmaxf(mx1, __shfl_xor_sync(0xffffffffu, mx1, 1));
        mx1 = fmaxf(mx1, __shfl_xor_sync(0xffffffffu, mx1, 2));

        float sum0 = 0.f, sum1 = 0.f;
        #pragma unroll
        for (int nt = 0; nt < 14; nt++) {
            float p0 = __expf(sacc[nt][0] - mx0);
            float p1 = __expf(sacc[nt][1] - mx0);
            float p2 = __expf(sacc[nt][2] - mx1);
            float p3 = __expf(sacc[nt][3] - mx1);
            sacc[nt][0] = p0; sacc[nt][1] = p1; sacc[nt][2] = p2; sacc[nt][3] = p3;
            sum0 += p0 + p1; sum1 += p2 + p3;
        }
        sum0 += __shfl_xor_sync(0xffffffffu, sum0, 1);
        sum0 += __shfl_xor_sync(0xffffffffu, sum0, 2);
        sum1 += __shfl_xor_sync(0xffffffffu, sum1, 1);
        sum1 += __shfl_xor_sync(0xffffffffu, sum1, 2);
        inva[mt][0] = 1.f / sum0;
        inva[mt][1] = 1.f / sum1;

        // ---- P @ V ----
        #pragma unroll
        for (int kt = 0; kt < 7; kt++) {
            uint32_t pa[4];
            pa[0] = pack_h2(sacc[2 * kt][0],     sacc[2 * kt][1]);
            pa[1] = pack_h2(sacc[2 * kt][2],     sacc[2 * kt][3]);
            pa[2] = pack_h2(sacc[2 * kt + 1][0], sacc[2 * kt + 1][1]);
            pa[3] = pack_h2(sacc[2 * kt + 1][2], sacc[2 * kt + 1][3]);
            #pragma unroll
            for (int nt2 = 0; nt2 < 4; nt2++) {
                int n = nt2 * 8 + bn;
                uint32_t b[2];
                b[0] = Vt2[n * 60 + kt * 8 + c4];
                b[1] = Vt2[n * 60 + kt * 8 + c4 + 4];
                mma_f16(ctxa[mt][nt2], pa, b);
            }
        }
    }

    // ---- normalize + store ctx ----
    #pragma unroll
    for (int mt = 0; mt < 2; mt++) {
        int r0 = wm0 + mt * 16 + bn, r1 = r0 + 8;
        #pragma unroll
        for (int nt2 = 0; nt2 < 4; nt2++) {
            int c = head * HD_ + nt2 * 8 + 2 * c4;
            if (r0 < 100)
                *(__half2*)(ctx + (size_t)(w * L_ + r0) * C_ + c) =
                    __floats2half2_rn(ctxa[mt][nt2][0] * inva[mt][0],
                                      ctxa[mt][nt2][1] * inva[mt][0]);
            if (r1 < 100)
                *(__half2*)(ctx + (size_t)(w * L_ + r1) * C_ + c) =
                    __floats2half2_rn(ctxa[mt][nt2][2] * inva[mt][1],
                                      ctxa[mt][nt2][3] * inva[mt][1]);
        }
    }
}

// ---------------- driver ----------------------------------------------------
extern "C" void kernel_launch(void* const* d_in, const int* in_sizes, int n_in,
                              void* d_out, int out_size)
{
    const float* hidden = (const float*)d_in[0];
    const float* ln1_g  = (const float*)d_in[1];
    const float* ln1_b  = (const float*)d_in[2];
    const float* wq = (const float*)d_in[3];
    const float* bq = (const float*)d_in[4];
    const float* wk = (const float*)d_in[5];
    const float* bk = (const float*)d_in[6];
    const float* wv = (const float*)d_in[7];
    const float* bv = (const float*)d_in[8];
    const float* wo = (const float*)d_in[9];
    const float* bo = (const float*)d_in[10];
    const float* table = (const float*)d_in[11];
    const float* ln2_g = (const float*)d_in[12];
    const float* ln2_b = (const float*)d_in[13];
    const float* w1 = (const float*)d_in[14];
    const float* b1 = (const float*)d_in[15];
    const float* w2 = (const float*)d_in[16];
    const float* b2 = (const float*)d_in[17];
    float* out = (float*)d_out;

    __half *pah, *pqh, *pkh, *pvh, *pch, *pfh, *pwh;
    float *po, *phs, *pbqkv;
    cudaGetSymbolAddress((void**)&pah, g_ah);
    cudaGetSymbolAddress((void**)&pqh, g_qh);
    cudaGetSymbolAddress((void**)&pkh, g_kh);
    cudaGetSymbolAddress((void**)&pvh, g_vh);
    cudaGetSymbolAddress((void**)&po,  g_o);
    cudaGetSymbolAddress((void**)&pch, g_ch);
    cudaGetSymbolAddress((void**)&phs, g_hs);
    cudaGetSymbolAddress((void**)&pfh, g_fh);
    cudaGetSymbolAddress((void**)&pwh, g_wh);
    cudaGetSymbolAddress((void**)&pbqkv, g_bqkv);

    __half* whqkv = pwh;
    __half* who = pwh + 786432;
    __half* wh1 = pwh + 1048576;
    __half* wh2 = pwh + 2097152;

    const int GSMEM = 3 * STG_W * 4;
    cudaFuncSetAttribute(gemm_h, cudaFuncAttributeMaxDynamicSharedMemorySize, GSMEM);

    // 0) weight/bias conversion
    convw_kernel<<<(C_ * C_ + 255) / 256, 256>>>(wq, whqkv, C_, C_, 3 * C_, 0);
    convw_kernel<<<(C_ * C_ + 255) / 256, 256>>>(wk, whqkv, C_, C_, 3 * C_, C_);
    convw_kernel<<<(C_ * C_ + 255) / 256, 256>>>(wv, whqkv, C_, C_, 3 * C_, 2 * C_);
    convw_kernel<<<(C_ * C_ + 255) / 256, 256>>>(wo, who, C_, C_, C_, 0);
    convw_kernel<<<(C_ * FF_ + 255) / 256, 256>>>(w1, wh1, C_, FF_, FF_, 0);
    convw_kernel<<<(FF_ * C_ + 255) / 256, 256>>>(w2, wh2, FF_, C_, C_, 0);
    concat_bias_kernel<<<6, 256>>>(bq, bk, bv, pbqkv);

    // 1) LN1 + shift + window partition -> g_ah
    ln_kernel<<<TOK_, 128>>>(hidden, ln1_g, ln1_b, pah);

    // 2) fused QKV projection -> half q/k/v
    gemm_h<<<dim3(TOK_ / BM, (3 * C_) / BN), 256, GSMEM>>>(
        pah, whqkv, pbqkv, nullptr, pqh, 3 * C_, C_, 3, pkh, pvh);

    // 3) tensor-core windowed attention -> g_ch
    attn_mma<<<dim3(B_ * NW_, NH_), 128>>>(pqh, pkh, pvh, table, pch);

    // 4) output projection -> g_o (f32)
    dim3 gp(TOK_ / BM, C_ / BN);
    gemm_h<<<gp, 256, GSMEM>>>(pch, who, bo, nullptr, po, C_, C_, 0, nullptr, nullptr);

    // 5) reverse + residual + LN2 -> g_hs, g_ah
    rev_res_ln_kernel<<<TOK_, 128>>>(hidden, po, ln2_g, ln2_b, phs, pah);

    // 6) FFN1 + GELU -> g_fh
    gemm_h<<<dim3(TOK_ / BM, FF_ / BN), 256, GSMEM>>>(
        pah, wh1, b1, nullptr, pfh, FF_, C_, 1, nullptr, nullptr);

    // 7) FFN2 + residual -> out
    gemm_h<<<gp, 256, GSMEM>>>(pfh, wh2, b2, phs, out, C_, FF_, 2, nullptr, nullptr);
}